// round 14
// baseline (speedup 1.0000x reference)
#include <cuda_runtime.h>
#include <cstdint>

// ---------------------------------------------------------------------------
// ODEFullBlock: encoder (conv1 fp32; conv2/conv3 TF32 mma) -> fused dopri5 ODE
// solve with TF32 tensor-core convs -> GN/relu -> mean -> linear
// B=256. ODE state [256,64,7,7]. ODE conv warps remapped to (m-pair, n-quarter)
// so each weight float4 feeds 4 mmas -> L2 weight traffic halved.
// ---------------------------------------------------------------------------

#define EPSV 1e-5f

// ---- scratch layout (floats) ----
#define OFF_B1   0UL                      // 14745600
#define OFF_B2   14745600UL               // 3686400
#define OFF_Y    18432000UL               // 802816
#define OFF_K    19234816UL               // 6*802816 = 4816896
#define OFF_WF1  24051712UL               // 9216 float4 = 36864 floats
#define OFF_WF2  24088576UL               // 36864
#define OFF_TW1  24125440UL               // 3136
#define OFF_TW2  24128576UL               // 3136
#define OFF_WC2  24131712UL               // 16384 float4 = 65536 floats
#define OFF_WC3  24197248UL               // 65536
#define SCRATCH_TOTAL 24262784UL

__device__ float g_scratch[SCRATCH_TOTAL];

// ---------------------------------------------------------------------------
// tf32 helpers
// ---------------------------------------------------------------------------
__device__ __forceinline__ uint32_t f2tf32(float x) {
    uint32_t r; asm("cvt.rna.tf32.f32 %0, %1;" : "=r"(r) : "f"(x)); return r;
}
__device__ __forceinline__ float rnd_tf32(float x) {
    return __uint_as_float(f2tf32(x));
}
__device__ __forceinline__ void mma_tf32(float c[4],
    uint32_t a0, uint32_t a1, uint32_t a2, uint32_t a3,
    uint32_t b0, uint32_t b1)
{
    asm volatile("mma.sync.aligned.m16n8k8.row.col.f32.tf32.tf32.f32 "
        "{%0,%1,%2,%3}, {%4,%5,%6,%7}, {%8,%9}, {%0,%1,%2,%3};"
        : "+f"(c[0]), "+f"(c[1]), "+f"(c[2]), "+f"(c[3])
        : "r"(a0), "r"(a1), "r"(a2), "r"(a3), "r"(b0), "r"(b1));
}

// ---------------------------------------------------------------------------
// group stats helpers (32 groups, 8 threads/group; threads 0..255)
// ---------------------------------------------------------------------------
__device__ __forceinline__ void stats98(const float* __restrict__ s,
                                        float* __restrict__ sm,
                                        float* __restrict__ si, int tid)
{
    int g = tid >> 3, l = tid & 7;
    const float* p = s + g * 98;
    float su = 0.f, sq = 0.f;
    for (int j = l; j < 98; j += 8) { float v = p[j]; su += v; sq += v * v; }
    su += __shfl_xor_sync(0xffffffffu, su, 1); sq += __shfl_xor_sync(0xffffffffu, sq, 1);
    su += __shfl_xor_sync(0xffffffffu, su, 2); sq += __shfl_xor_sync(0xffffffffu, sq, 2);
    su += __shfl_xor_sync(0xffffffffu, su, 4); sq += __shfl_xor_sync(0xffffffffu, sq, 4);
    if (l == 0) {
        float m = su * (1.f / 98.f);
        float var = sq * (1.f / 98.f) - m * m;
        sm[g] = m; si[g] = rsqrtf(var + EPSV);
    }
}
__device__ __forceinline__ void stats450(const float* __restrict__ s,
                                         float* __restrict__ sm,
                                         float* __restrict__ si, int tid)
{
    int g = tid >> 3, l = tid & 7;
    const float* p = s + g * 450;
    float su = 0.f, sq = 0.f;
    for (int j = l; j < 450; j += 8) { float v = p[j]; su += v; sq += v * v; }
    su += __shfl_xor_sync(0xffffffffu, su, 1); sq += __shfl_xor_sync(0xffffffffu, sq, 1);
    su += __shfl_xor_sync(0xffffffffu, su, 2); sq += __shfl_xor_sync(0xffffffffu, sq, 2);
    su += __shfl_xor_sync(0xffffffffu, su, 4); sq += __shfl_xor_sync(0xffffffffu, sq, 4);
    if (l == 0) {
        float m = su * (1.f / 450.f);
        float var = sq * (1.f / 450.f) - m * m;
        sm[g] = m; si[g] = rsqrtf(var + EPSV);
    }
}

// ---------------------------------------------------------------------------
// prep: fragment-permute all tensor-core weights (single tf32, pair-packed)
// ---------------------------------------------------------------------------
__global__ void k_prep(const float* __restrict__ occ1_w, const float* __restrict__ occ2_w,
                       const float* __restrict__ c2_w, const float* __restrict__ c3_w,
                       float4* __restrict__ WF1, float4* __restrict__ WF2,
                       float* __restrict__ tw1, float* __restrict__ tw2,
                       float4* __restrict__ WC2, float4* __restrict__ WC3)
{
    int i = blockIdx.x * 256 + threadIdx.x;
    if (i < 9216) {
        int lane = i & 31, rem = i >> 5;
        int jp = rem & 3, tk = rem >> 2;
        int k = tk & 7, tap = tk >> 3;
        int ic0 = k * 8 + (lane & 3);
        int oc0 = 2 * jp * 8 + (lane >> 2);
        int oc1 = oc0 + 8;
        WF1[i] = make_float4(
            rnd_tf32(occ1_w[(oc0 * 65 + 1 + ic0) * 9 + tap]),
            rnd_tf32(occ1_w[(oc0 * 65 + 1 + ic0 + 4) * 9 + tap]),
            rnd_tf32(occ1_w[(oc1 * 65 + 1 + ic0) * 9 + tap]),
            rnd_tf32(occ1_w[(oc1 * 65 + 1 + ic0 + 4) * 9 + tap]));
        WF2[i] = make_float4(
            rnd_tf32(occ2_w[(oc0 * 65 + 1 + ic0) * 9 + tap]),
            rnd_tf32(occ2_w[(oc0 * 65 + 1 + ic0 + 4) * 9 + tap]),
            rnd_tf32(occ2_w[(oc1 * 65 + 1 + ic0) * 9 + tap]),
            rnd_tf32(occ2_w[(oc1 * 65 + 1 + ic0 + 4) * 9 + tap]));
    }
    if (i < 16384) {
        int lane = i & 31, rem = i >> 5;
        int p = rem & 3, tk = rem >> 2;
        int tap = tk & 15, chunk = tk >> 4;
        int ic = chunk * 8 + (lane & 3);
        int n0 = 2 * p * 8 + (lane >> 2);
        int n1 = n0 + 8;
        WC2[i] = make_float4(
            rnd_tf32(c2_w[(n0 * 64 + ic) * 16 + tap]),
            rnd_tf32(c2_w[(n0 * 64 + ic + 4) * 16 + tap]),
            rnd_tf32(c2_w[(n1 * 64 + ic) * 16 + tap]),
            rnd_tf32(c2_w[(n1 * 64 + ic + 4) * 16 + tap]));
        WC3[i] = make_float4(
            rnd_tf32(c3_w[(n0 * 64 + ic) * 16 + tap]),
            rnd_tf32(c3_w[(n0 * 64 + ic + 4) * 16 + tap]),
            rnd_tf32(c3_w[(n1 * 64 + ic) * 16 + tap]),
            rnd_tf32(c3_w[(n1 * 64 + ic + 4) * 16 + tap]));
    }
    if (i < 3136) {
        int oc = i / 49, pos = i % 49, oy = pos / 7, ox = pos % 7;
        float s1 = 0.f, s2 = 0.f;
        for (int ky = 0; ky < 3; ky++)
            for (int kx = 0; kx < 3; kx++) {
                int iy = oy + ky - 1, ix = ox + kx - 1;
                if ((unsigned)iy < 7u && (unsigned)ix < 7u) {
                    s1 += occ1_w[(oc * 65) * 9 + ky * 3 + kx];
                    s2 += occ2_w[(oc * 65) * 9 + ky * 3 + kx];
                }
            }
        tw1[i] = s1; tw2[i] = s2;
    }
}

// ---------------------------------------------------------------------------
// conv1 3->64 3x3 s1 p0 on 32x32 -> 30x30, fused GN + relu (fp32)
// ---------------------------------------------------------------------------
__global__ __launch_bounds__(128) void k_conv1(
    const float* __restrict__ x, const float* __restrict__ w,
    const float* __restrict__ bias, const float* __restrict__ gw,
    const float* __restrict__ gb, float* __restrict__ out)
{
    __shared__ float s_in[3 * 32 * 32];
    __shared__ float s_out[1800];
    __shared__ float s_w[54];
    __shared__ float sred[8];
    __shared__ float s_stats[2];
    int g = blockIdx.x, b = blockIdx.y, tid = threadIdx.x;
    for (int i = tid; i < 3072; i += 128) s_in[i] = x[b * 3072 + i];
    if (tid < 54) {
        int oc = 2 * g + tid / 27;
        s_w[tid] = w[oc * 27 + (tid % 27)];
    }
    __syncthreads();
    float mysum = 0.f, mysq = 0.f;
    for (int idx = tid; idx < 1800; idx += 128) {
        int c = idx / 900, pos = idx % 900, oy = pos / 30, ox = pos % 30;
        float acc = __ldg(&bias[2 * g + c]);
        const float* wp = &s_w[c * 27];
        #pragma unroll
        for (int ic = 0; ic < 3; ic++)
            #pragma unroll
            for (int ky = 0; ky < 3; ky++)
                #pragma unroll
                for (int kx = 0; kx < 3; kx++)
                    acc += wp[ic * 9 + ky * 3 + kx] * s_in[ic * 1024 + (oy + ky) * 32 + (ox + kx)];
        s_out[idx] = acc; mysum += acc; mysq += acc * acc;
    }
    #pragma unroll
    for (int o = 16; o > 0; o >>= 1) {
        mysum += __shfl_xor_sync(0xffffffffu, mysum, o);
        mysq  += __shfl_xor_sync(0xffffffffu, mysq,  o);
    }
    if ((tid & 31) == 0) { sred[(tid >> 5) * 2] = mysum; sred[(tid >> 5) * 2 + 1] = mysq; }
    __syncthreads();
    if (tid == 0) {
        float s = sred[0] + sred[2] + sred[4] + sred[6];
        float q = sred[1] + sred[3] + sred[5] + sred[7];
        float m = s / 1800.f, var = q / 1800.f - m * m;
        s_stats[0] = m; s_stats[1] = rsqrtf(var + EPSV);
    }
    __syncthreads();
    float m = s_stats[0], inv = s_stats[1];
    for (int idx = tid; idx < 1800; idx += 128) {
        int c = idx / 900, oc = 2 * g + c;
        float v = (s_out[idx] - m) * inv * __ldg(&gw[oc]) + __ldg(&gb[oc]);
        out[((size_t)b * 64 + oc) * 900 + (idx % 900)] = fmaxf(v, 0.f);
    }
}

// ---------------------------------------------------------------------------
// conv2 TF32: 64->64 4x4 s2 p1 on 30x30 -> 15x15, fused GN + relu.
// ---------------------------------------------------------------------------
#define C2_SMEM_FLOATS (10240 + 14400 + 64)
__global__ __launch_bounds__(256, 2) void k_conv2tc(
    const float* __restrict__ in, const float4* __restrict__ WC2,
    const float* __restrict__ bias, const float* __restrict__ gw,
    const float* __restrict__ gb, float* __restrict__ out)
{
    extern __shared__ float sc2[];
    float* sIn  = sc2;            // 1024 positions x stride 10 (tf32-rounded)
    float* sOut = sc2 + 10240;
    float* sm   = sc2 + 10240 + 14400;
    float* si   = sm + 32;
    const int b = blockIdx.x, tid = threadIdx.x;
    const int lane = tid & 31, wid = tid >> 5;
    const int icq = lane & 3;

    const int r00 = wid * 16 + (lane >> 2), r01 = r00 + 8;       // always < 225
    const int mt1 = wid + 8;
    const bool hasmt1 = mt1 < 15;
    const int r10 = mt1 * 16 + (lane >> 2), r11 = r10 + 8;
    const int p10 = min(r10, 224), p11 = min(r11, 224);
    const int oy00 = r00 / 15, ox00 = r00 % 15;
    const int oy01 = r01 / 15, ox01 = r01 % 15;
    const int oy10 = p10 / 15, ox10 = p10 % 15;
    const int oy11 = p11 / 15, ox11 = p11 % 15;

    float acc0[8][4], acc1[8][4];
    #pragma unroll
    for (int j = 0; j < 8; j++)
        #pragma unroll
        for (int q = 0; q < 4; q++) { acc0[j][q] = 0.f; acc1[j][q] = 0.f; }

    const float* inb = in + (size_t)b * 57600;
    for (int chunk = 0; chunk < 8; chunk++) {
        __syncthreads();
        for (int idx = tid; idx < 8192; idx += 256) {
            int icL = idx >> 10, pos = idx & 1023;
            int iy = pos >> 5, ix = pos & 31;
            int riy = iy - 1, rix = ix - 1;
            sIn[pos * 10 + icL] = ((unsigned)riy < 30u && (unsigned)rix < 30u)
                        ? rnd_tf32(inb[(chunk * 8 + icL) * 900 + riy * 30 + rix]) : 0.f;
        }
        __syncthreads();
        #pragma unroll 4
        for (int tap = 0; tap < 16; tap++) {
            int ky = tap >> 2, kx = tap & 3;
            int o00 = ((2 * oy00 + ky) * 32 + 2 * ox00 + kx) * 10 + icq;
            int o01 = ((2 * oy01 + ky) * 32 + 2 * ox01 + kx) * 10 + icq;
            int o10 = ((2 * oy10 + ky) * 32 + 2 * ox10 + kx) * 10 + icq;
            int o11 = ((2 * oy11 + ky) * 32 + 2 * ox11 + kx) * 10 + icq;
            uint32_t aA0 = __float_as_uint(sIn[o00]), aA1 = __float_as_uint(sIn[o01]);
            uint32_t aA2 = __float_as_uint(sIn[o00 + 4]), aA3 = __float_as_uint(sIn[o01 + 4]);
            uint32_t aB0 = __float_as_uint(sIn[o10]), aB1 = __float_as_uint(sIn[o11]);
            uint32_t aB2 = __float_as_uint(sIn[o10 + 4]), aB3 = __float_as_uint(sIn[o11 + 4]);
            const float4* wf = WC2 + ((size_t)(chunk * 16 + tap) * 4) * 32 + lane;
            #pragma unroll
            for (int p = 0; p < 4; p++) {
                float4 bv = __ldg(&wf[p * 32]);
                uint32_t b0 = __float_as_uint(bv.x), b1 = __float_as_uint(bv.y);
                uint32_t b2 = __float_as_uint(bv.z), b3 = __float_as_uint(bv.w);
                mma_tf32(acc0[2 * p],     aA0, aA1, aA2, aA3, b0, b1);
                mma_tf32(acc0[2 * p + 1], aA0, aA1, aA2, aA3, b2, b3);
                mma_tf32(acc1[2 * p],     aB0, aB1, aB2, aB3, b0, b1);
                mma_tf32(acc1[2 * p + 1], aB0, aB1, aB2, aB3, b2, b3);
            }
        }
    }
    __syncthreads();
    // scatter (bias included so GN stats see biased values)
    #pragma unroll
    for (int j = 0; j < 8; j++) {
        int n0 = j * 8 + 2 * (lane & 3);
        float b0 = __ldg(&bias[n0]), b1 = __ldg(&bias[n0 + 1]);
        sOut[n0 * 225 + r00] = acc0[j][0] + b0;
        sOut[(n0 + 1) * 225 + r00] = acc0[j][1] + b1;
        sOut[n0 * 225 + r01] = acc0[j][2] + b0;
        sOut[(n0 + 1) * 225 + r01] = acc0[j][3] + b1;
        if (hasmt1) {
            if (r10 < 225) {
                sOut[n0 * 225 + r10] = acc1[j][0] + b0;
                sOut[(n0 + 1) * 225 + r10] = acc1[j][1] + b1;
            }
            if (r11 < 225) {
                sOut[n0 * 225 + r11] = acc1[j][2] + b0;
                sOut[(n0 + 1) * 225 + r11] = acc1[j][3] + b1;
            }
        }
    }
    __syncthreads();
    stats450(sOut, sm, si, tid);
    __syncthreads();
    for (int i2 = tid; i2 < 14400; i2 += 256) {
        int oc = i2 / 225, g = oc >> 1;
        float v = (sOut[i2] - sm[g]) * si[g] * __ldg(&gw[oc]) + __ldg(&gb[oc]);
        out[(size_t)b * 14400 + i2] = fmaxf(v, 0.f);
    }
}

// ---------------------------------------------------------------------------
// conv3 TF32: 64->64 4x4 s2 p1 on 15x15 -> 7x7 (no GN).
// ---------------------------------------------------------------------------
#define C3_SMEM_FLOATS (256 * 66)
__global__ __launch_bounds__(256) void k_conv3tc(
    const float* __restrict__ in, const float4* __restrict__ WC3,
    const float* __restrict__ bias, float* __restrict__ out)
{
    extern __shared__ float sIn3[];   // 256 positions (16x16 padded) x stride 66
    const int b = blockIdx.x, tid = threadIdx.x;
    const int lane = tid & 31, wid = tid >> 5;
    const int mt = wid >> 1, nh = wid & 1;
    const int icq = lane & 3;
    const int r0 = mt * 16 + (lane >> 2), r1 = r0 + 8;
    const int p0 = min(r0, 48), p1 = min(r1, 48);
    const int oy0 = p0 / 7, ox0 = p0 % 7;
    const int oy1 = p1 / 7, ox1 = p1 % 7;

    float acc[4][4];
    #pragma unroll
    for (int j = 0; j < 4; j++)
        #pragma unroll
        for (int q = 0; q < 4; q++) acc[j][q] = 0.f;

    const float* inb = in + (size_t)b * 14400;
    for (int idx = tid; idx < 16384; idx += 256) {
        int ic = idx >> 8, pos = idx & 255;
        int iy = pos >> 4, ix = pos & 15;
        int riy = iy - 1, rix = ix - 1;
        sIn3[pos * 66 + ic] = ((unsigned)riy < 15u && (unsigned)rix < 15u)
                    ? rnd_tf32(inb[ic * 225 + riy * 15 + rix]) : 0.f;
    }
    __syncthreads();

    for (int chunk = 0; chunk < 8; chunk++) {
        #pragma unroll 4
        for (int tap = 0; tap < 16; tap++) {
            int ky = tap >> 2, kx = tap & 3;
            int o0 = ((2 * oy0 + ky) * 16 + 2 * ox0 + kx) * 66 + chunk * 8 + icq;
            int o1 = ((2 * oy1 + ky) * 16 + 2 * ox1 + kx) * 66 + chunk * 8 + icq;
            uint32_t a0 = __float_as_uint(sIn3[o0]), a1 = __float_as_uint(sIn3[o1]);
            uint32_t a2 = __float_as_uint(sIn3[o0 + 4]), a3 = __float_as_uint(sIn3[o1 + 4]);
            const float4* wf = WC3 + ((size_t)(chunk * 16 + tap) * 4 + nh * 2) * 32 + lane;
            #pragma unroll
            for (int p = 0; p < 2; p++) {
                float4 bv = __ldg(&wf[p * 32]);
                mma_tf32(acc[2 * p],     a0, a1, a2, a3,
                         __float_as_uint(bv.x), __float_as_uint(bv.y));
                mma_tf32(acc[2 * p + 1], a0, a1, a2, a3,
                         __float_as_uint(bv.z), __float_as_uint(bv.w));
            }
        }
    }
    #pragma unroll
    for (int j = 0; j < 4; j++) {
        int n = nh * 32 + j * 8 + 2 * (lane & 3);
        float b0 = __ldg(&bias[n]), b1 = __ldg(&bias[n + 1]);
        float* ob = out + (size_t)b * 3136;
        if (r0 < 49) {
            ob[n * 49 + r0] = acc[j][0] + b0;
            ob[(n + 1) * 49 + r0] = acc[j][1] + b1;
        }
        if (r1 < 49) {
            ob[n * 49 + r1] = acc[j][2] + b0;
            ob[(n + 1) * 49 + r1] = acc[j][3] + b1;
        }
    }
}

// ---------------------------------------------------------------------------
// fused ODE solver, 256 threads/image (8 warps). Warp = (m-pair mp=wid>>2,
// n-quarter nq=wid&3): each weight float4 feeds 4 mmas (2 m-tiles x 2 n8).
// k-write fused with next stage-combine (7 barriers/stage).
// ---------------------------------------------------------------------------
#define S_Y    0
#define S_ACT  3136
#define S_B    (3136 + 6936)
#define S_SM   (3136 + 6936 + 3136)
#define S_SI   (S_SM + 32)
#define ODE_SMEM_FLOATS (S_SI + 32)

__device__ __forceinline__ void conv_mma(
    const float* __restrict__ sAct, float* __restrict__ sB,
    const float4* __restrict__ WF, const float* __restrict__ tW,
    const float* __restrict__ bias, float t,
    int pl0, int ph0, int pl1, int ph1,
    int rl0, int rh0, int rl1, int rh1,
    int c0i, int nq, int lane)
{
    float acc[2][2][4];   // [m-tile][n8][frag]
    #pragma unroll
    for (int p = 0; p < 2; p++) {
        int n0 = (nq * 2 + p) * 8 + 2 * (lane & 3);
        float b0v = __ldg(&bias[n0]), b1v = __ldg(&bias[n0 + 1]);
        acc[0][p][0] = (rl0 < 49) ? b0v + t * __ldg(&tW[n0 * 49 + rl0]) : 0.f;
        acc[0][p][1] = (rl0 < 49) ? b1v + t * __ldg(&tW[(n0 + 1) * 49 + rl0]) : 0.f;
        acc[0][p][2] = (rh0 < 49) ? b0v + t * __ldg(&tW[n0 * 49 + rh0]) : 0.f;
        acc[0][p][3] = (rh0 < 49) ? b1v + t * __ldg(&tW[(n0 + 1) * 49 + rh0]) : 0.f;
        acc[1][p][0] = (rl1 < 49) ? b0v + t * __ldg(&tW[n0 * 49 + rl1]) : 0.f;
        acc[1][p][1] = (rl1 < 49) ? b1v + t * __ldg(&tW[(n0 + 1) * 49 + rl1]) : 0.f;
        acc[1][p][2] = (rh1 < 49) ? b0v + t * __ldg(&tW[n0 * 49 + rh1]) : 0.f;
        acc[1][p][3] = (rh1 < 49) ? b1v + t * __ldg(&tW[(n0 + 1) * 49 + rh1]) : 0.f;
    }
    #pragma unroll 3
    for (int tap = 0; tap < 9; tap++) {
        int shift = (tap / 3) * 9 + (tap % 3) - 10;
        const float* aL0 = sAct + (pl0 + shift) * 68 + c0i;
        const float* aH0 = sAct + (ph0 + shift) * 68 + c0i;
        const float* aL1 = sAct + (pl1 + shift) * 68 + c0i;
        const float* aH1 = sAct + (ph1 + shift) * 68 + c0i;
        const float4* wf = WF + ((size_t)(tap * 8) * 4 + nq) * 32 + lane;
        #pragma unroll
        for (int k = 0; k < 8; k++) {
            float4 bv = __ldg(&wf[(size_t)(k * 4) * 32]);
            uint32_t w0 = __float_as_uint(bv.x), w1 = __float_as_uint(bv.y);
            uint32_t w2 = __float_as_uint(bv.z), w3 = __float_as_uint(bv.w);
            uint32_t a0 = __float_as_uint(aL0[k * 8]);
            uint32_t a1 = __float_as_uint(aH0[k * 8]);
            uint32_t a2 = __float_as_uint(aL0[k * 8 + 4]);
            uint32_t a3 = __float_as_uint(aH0[k * 8 + 4]);
            mma_tf32(acc[0][0], a0, a1, a2, a3, w0, w1);
            mma_tf32(acc[0][1], a0, a1, a2, a3, w2, w3);
            uint32_t c0 = __float_as_uint(aL1[k * 8]);
            uint32_t c1 = __float_as_uint(aH1[k * 8]);
            uint32_t c2 = __float_as_uint(aL1[k * 8 + 4]);
            uint32_t c3 = __float_as_uint(aH1[k * 8 + 4]);
            mma_tf32(acc[1][0], c0, c1, c2, c3, w0, w1);
            mma_tf32(acc[1][1], c0, c1, c2, c3, w2, w3);
        }
    }
    #pragma unroll
    for (int p = 0; p < 2; p++) {
        int n0 = (nq * 2 + p) * 8 + 2 * (lane & 3);
        if (rl0 < 49) {
            sB[n0 * 49 + rl0] = acc[0][p][0];
            sB[(n0 + 1) * 49 + rl0] = acc[0][p][1];
        }
        if (rh0 < 49) {
            sB[n0 * 49 + rh0] = acc[0][p][2];
            sB[(n0 + 1) * 49 + rh0] = acc[0][p][3];
        }
        if (rl1 < 49) {
            sB[n0 * 49 + rl1] = acc[1][p][0];
            sB[(n0 + 1) * 49 + rl1] = acc[1][p][1];
        }
        if (rh1 < 49) {
            sB[n0 * 49 + rh1] = acc[1][p][2];
            sB[(n0 + 1) * 49 + rh1] = acc[1][p][3];
        }
    }
}

__global__ __launch_bounds__(256, 2) void k_ode(
    float* __restrict__ Yg, float* __restrict__ Kb,
    const float4* __restrict__ WF1, const float* __restrict__ TW1,
    const float* __restrict__ occ1_b,
    const float4* __restrict__ WF2, const float* __restrict__ TW2,
    const float* __restrict__ occ2_b,
    const float* __restrict__ oa_w, const float* __restrict__ oa_b,
    const float* __restrict__ ob_w, const float* __restrict__ ob_b,
    const float* __restrict__ oc_w, const float* __restrict__ oc_b)
{
    extern __shared__ float sd[];
    float* sY   = sd + S_Y;
    float* sAct = sd + S_ACT;
    float* sB   = sd + S_B;
    float* sm   = sd + S_SM;
    float* si   = sd + S_SI;

    const int b = blockIdx.x, tid = threadIdx.x;
    const int lane = tid & 31, wid = tid >> 5;
    const int mp = wid >> 2, nq = wid & 3;
    const int rl0 = (2 * mp) * 16 + (lane >> 2),     rh0 = rl0 + 8;
    const int rl1 = (2 * mp + 1) * 16 + (lane >> 2), rh1 = rl1 + 8;
    const int pl0 = (rl0 < 49) ? (rl0 / 7) * 9 + rl0 % 7 + 10 : 91;
    const int ph0 = (rh0 < 49) ? (rh0 / 7) * 9 + rh0 % 7 + 10 : 91;
    const int pl1 = (rl1 < 49) ? (rl1 / 7) * 9 + rl1 % 7 + 10 : 91;
    const int ph1 = (rh1 < 49) ? (rh1 / 7) * 9 + rh1 % 7 + 10 : 91;
    const int c0i = lane & 3;
    const size_t base = (size_t)b * 3136;
    const int sg = tid >> 3, sl = tid & 7;   // stats group mapping

    // per-thread GN(oc) params for the fused epilogue (group sg = channels 2sg, 2sg+1)
    const float ocw0 = __ldg(&oc_w[2 * sg]),     ocb0 = __ldg(&oc_b[2 * sg]);
    const float ocw1 = __ldg(&oc_w[2 * sg + 1]), ocb1 = __ldg(&oc_b[2 * sg + 1]);

    const double hh = 1.0 / 6.0;
    double Atab[6][5] = {
        {0, 0, 0, 0, 0},
        {1.0 / 5.0, 0, 0, 0, 0},
        {3.0 / 40.0, 9.0 / 40.0, 0, 0, 0},
        {44.0 / 45.0, -56.0 / 15.0, 32.0 / 9.0, 0, 0},
        {19372.0 / 6561.0, -25360.0 / 2187.0, 64448.0 / 6561.0, -212.0 / 729.0, 0},
        {9017.0 / 3168.0, -355.0 / 33.0, 46732.0 / 5247.0, 49.0 / 176.0, -5103.0 / 18656.0}
    };
    double Ctab[6] = {0.0, 1.0 / 5.0, 3.0 / 10.0, 4.0 / 5.0, 8.0 / 9.0, 1.0};

    for (int i = tid; i < 6936; i += 256) sAct[i] = 0.f;
    for (int i = tid; i < 3136; i += 256) sY[i] = Yg[base + i];
    __syncthreads();

    // initial combine (step 0, stage 0): sB = sY, fused stats
    {
        float su = 0.f, sq = 0.f;
        const int ibase = sg * 98;
        for (int j = sl; j < 98; j += 8) {
            float v = sY[ibase + j];
            sB[ibase + j] = v;
            su += v; sq += v * v;
        }
        su += __shfl_xor_sync(0xffffffffu, su, 1); sq += __shfl_xor_sync(0xffffffffu, sq, 1);
        su += __shfl_xor_sync(0xffffffffu, su, 2); sq += __shfl_xor_sync(0xffffffffu, sq, 2);
        su += __shfl_xor_sync(0xffffffffu, su, 4); sq += __shfl_xor_sync(0xffffffffu, sq, 4);
        if (sl == 0) {
            float m = su * (1.f / 98.f);
            float var = sq * (1.f / 98.f) - m * m;
            sm[sg] = m; si[sg] = rsqrtf(var + EPSV);
        }
    }
    __syncthreads();

    for (int step = 0; step < 6; step++) {
        double t0 = (double)step * hh;
        for (int s = 0; s < 6; s++) {
            float t = (float)(t0 + Ctab[s] * hh);

            // GN(oa)+relu -> sAct interior (tf32-pre-rounded)
            for (int i = tid; i < 3136; i += 256) {
                int pos = i >> 6, c = i & 63;
                int pb = (pos / 7) * 9 + pos % 7 + 10;
                int g = c >> 1;
                float v = (sB[c * 49 + pos] - sm[g]) * si[g] * __ldg(&oa_w[c]) + __ldg(&oa_b[c]);
                sAct[pb * 68 + c] = rnd_tf32(fmaxf(v, 0.f));
            }
            __syncthreads();
            conv_mma(sAct, sB, WF1, TW1, occ1_b, t,
                     pl0, ph0, pl1, ph1, rl0, rh0, rl1, rh1, c0i, nq, lane);
            __syncthreads();
            stats98(sB, sm, si, tid);
            __syncthreads();
            for (int i = tid; i < 3136; i += 256) {
                int pos = i >> 6, c = i & 63;
                int pb = (pos / 7) * 9 + pos % 7 + 10;
                int g = c >> 1;
                float v = (sB[c * 49 + pos] - sm[g]) * si[g] * __ldg(&ob_w[c]) + __ldg(&ob_b[c]);
                sAct[pb * 68 + c] = rnd_tf32(fmaxf(v, 0.f));
            }
            __syncthreads();
            conv_mma(sAct, sB, WF2, TW2, occ2_b, t,
                     pl0, ph0, pl1, ph1, rl0, rh0, rl1, rh1, c0i, nq, lane);
            __syncthreads();
            stats98(sB, sm, si, tid);
            __syncthreads();

            // fused epilogue: k = GN(oc)(sB); write K_s; combine next stage
            // (newest K from register); next-stage stats. Bitwise-identical.
            {
                float m = sm[sg], inv = si[sg];
                float su = 0.f, sq = 0.f;
                const int ibase = sg * 98;
                if (s < 5) {
                    float cn0 = (float)(hh * Atab[s + 1][0]);
                    float cn1 = (float)(hh * Atab[s + 1][1]);
                    float cn2 = (float)(hh * Atab[s + 1][2]);
                    float cn3 = (float)(hh * Atab[s + 1][3]);
                    float cn4 = (float)(hh * Atab[s + 1][4]);
                    float cl = (s == 0) ? cn0 : (s == 1) ? cn1 : (s == 2) ? cn2
                             : (s == 3) ? cn3 : cn4;
                    float* Ks = Kb + (size_t)s * 802816 + base;
                    for (int j = sl; j < 98; j += 8) {
                        int i = ibase + j;
                        float ocw = (j < 49) ? ocw0 : ocw1;
                        float ocb = (j < 49) ? ocb0 : ocb1;
                        float kk = (sB[i] - m) * inv * ocw + ocb;
                        Ks[i] = kk;
                        float v = sY[i];
                        if (s >= 1) v += cn0 * Kb[base + i];
                        if (s >= 2) v += cn1 * Kb[802816 + base + i];
                        if (s >= 3) v += cn2 * Kb[2 * 802816 + base + i];
                        if (s >= 4) v += cn3 * Kb[3 * 802816 + base + i];
                        v += cl * kk;
                        sB[i] = v;
                        su += v; sq += v * v;
                    }
                } else {
                    float b1 = (float)(hh * 35.0 / 384.0);
                    float b3 = (float)(hh * 500.0 / 1113.0);
                    float b4 = (float)(hh * 125.0 / 192.0);
                    float b5 = (float)(hh * -2187.0 / 6784.0);
                    float b6 = (float)(hh * 11.0 / 84.0);
                    for (int j = sl; j < 98; j += 8) {
                        int i = ibase + j;
                        float ocw = (j < 49) ? ocw0 : ocw1;
                        float ocb = (j < 49) ? ocb0 : ocb1;
                        float k6 = (sB[i] - m) * inv * ocw + ocb;
                        float e = b1 * Kb[base + i]
                                + b3 * Kb[2 * 802816 + base + i]
                                + b4 * Kb[3 * 802816 + base + i]
                                + b5 * Kb[4 * 802816 + base + i]
                                + b6 * k6;
                        float v = sY[i] + e;
                        sY[i] = v;
                        sB[i] = v;
                        su += v; sq += v * v;
                    }
                }
                su += __shfl_xor_sync(0xffffffffu, su, 1); sq += __shfl_xor_sync(0xffffffffu, sq, 1);
                su += __shfl_xor_sync(0xffffffffu, su, 2); sq += __shfl_xor_sync(0xffffffffu, sq, 2);
                su += __shfl_xor_sync(0xffffffffu, su, 4); sq += __shfl_xor_sync(0xffffffffu, sq, 4);
                if (sl == 0) {
                    float mm = su * (1.f / 98.f);
                    float var = sq * (1.f / 98.f) - mm * mm;
                    sm[sg] = mm; si[sg] = rsqrtf(var + EPSV);
                }
            }
            __syncthreads();
        }
    }
    for (int i = tid; i < 3136; i += 256) Yg[base + i] = sY[i];
}

// ---------------------------------------------------------------------------
// tail: GN(g3)+relu -> spatial mean -> linear(64->10)
// ---------------------------------------------------------------------------
__global__ __launch_bounds__(256) void k_tail(
    const float* __restrict__ y, const float* __restrict__ gw,
    const float* __restrict__ gb, const float* __restrict__ lw,
    const float* __restrict__ lb, float* __restrict__ out)
{
    __shared__ float s[3136];
    __shared__ float sm[32], si[32];
    __shared__ float cm[64];
    int b = blockIdx.x, tid = threadIdx.x;
    const size_t base = (size_t)b * 3136;
    for (int i = tid; i < 3136; i += 256) s[i] = y[base + i];
    __syncthreads();
    stats98(s, sm, si, tid);
    __syncthreads();
    if (tid < 64) {
        int c = tid, g = c >> 1;
        float w = gw[c], bb = gb[c], m = sm[g], inv = si[g];
        float su = 0.f;
        #pragma unroll
        for (int j = 0; j < 49; j++)
            su += fmaxf((s[c * 49 + j] - m) * inv * w + bb, 0.f);
        cm[c] = su * (1.f / 49.f);
    }
    __syncthreads();
    if (tid < 10) {
        float o = lb[tid];
        #pragma unroll
        for (int c = 0; c < 64; c++) o += cm[c] * lw[tid * 64 + c];
        out[b * 10 + tid] = o;
    }
}

// ---------------------------------------------------------------------------
// host launcher
// ---------------------------------------------------------------------------
extern "C" void kernel_launch(void* const* d_in, const int* in_sizes, int n_in,
                              void* d_out, int out_size)
{
    const float* x      = (const float*)d_in[0];
    const float* c1_w   = (const float*)d_in[1];
    const float* c1_b   = (const float*)d_in[2];
    const float* g1_w   = (const float*)d_in[3];
    const float* g1_b   = (const float*)d_in[4];
    const float* c2_w   = (const float*)d_in[5];
    const float* c2_b   = (const float*)d_in[6];
    const float* g2_w   = (const float*)d_in[7];
    const float* g2_b   = (const float*)d_in[8];
    const float* c3_w   = (const float*)d_in[9];
    const float* c3_b   = (const float*)d_in[10];
    const float* oa_w   = (const float*)d_in[11];
    const float* oa_b   = (const float*)d_in[12];
    const float* occ1_w = (const float*)d_in[13];
    const float* occ1_b = (const float*)d_in[14];
    const float* ob_w   = (const float*)d_in[15];
    const float* ob_b   = (const float*)d_in[16];
    const float* occ2_w = (const float*)d_in[17];
    const float* occ2_b = (const float*)d_in[18];
    const float* oc_w   = (const float*)d_in[19];
    const float* oc_b   = (const float*)d_in[20];
    const float* g3_w   = (const float*)d_in[21];
    const float* g3_b   = (const float*)d_in[22];
    const float* lin_w  = (const float*)d_in[23];
    const float* lin_b  = (const float*)d_in[24];

    float* S = nullptr;
    cudaGetSymbolAddress((void**)&S, g_scratch);
    float*  B1  = S + OFF_B1;
    float*  B2  = S + OFF_B2;
    float*  Y   = S + OFF_Y;
    float*  Kb  = S + OFF_K;
    float4* WF1 = (float4*)(S + OFF_WF1);
    float4* WF2 = (float4*)(S + OFF_WF2);
    float*  TW1 = S + OFF_TW1;
    float*  TW2 = S + OFF_TW2;
    float4* WC2 = (float4*)(S + OFF_WC2);
    float4* WC3 = (float4*)(S + OFF_WC3);

    cudaFuncSetAttribute(k_ode, cudaFuncAttributeMaxDynamicSharedMemorySize,
                         ODE_SMEM_FLOATS * (int)sizeof(float));
    cudaFuncSetAttribute(k_conv2tc, cudaFuncAttributeMaxDynamicSharedMemorySize,
                         C2_SMEM_FLOATS * (int)sizeof(float));
    cudaFuncSetAttribute(k_conv3tc, cudaFuncAttributeMaxDynamicSharedMemorySize,
                         C3_SMEM_FLOATS * (int)sizeof(float));

    k_prep<<<64, 256>>>(occ1_w, occ2_w, c2_w, c3_w, WF1, WF2, TW1, TW2, WC2, WC3);
    k_conv1<<<dim3(32, 256), 128>>>(x, c1_w, c1_b, g1_w, g1_b, B1);
    k_conv2tc<<<256, 256, C2_SMEM_FLOATS * sizeof(float)>>>(B1, WC2, c2_b, g2_w, g2_b, B2);
    k_conv3tc<<<256, 256, C3_SMEM_FLOATS * sizeof(float)>>>(B2, WC3, c3_b, Y);
    k_ode<<<256, 256, ODE_SMEM_FLOATS * sizeof(float)>>>(
        Y, Kb, WF1, TW1, occ1_b, WF2, TW2, occ2_b,
        oa_w, oa_b, ob_w, ob_b, oc_w, oc_b);
    k_tail<<<256, 256>>>(Y, g3_w, g3_b, lin_w, lin_b, (float*)d_out);
}

// round 15
// speedup vs baseline: 1.1132x; 1.1132x over previous
#include <cuda_runtime.h>
#include <cstdint>

// ---------------------------------------------------------------------------
// ODEFullBlock: encoder (conv1 fp32; conv2/conv3 TF32 mma) -> fused dopri5 ODE
// solve with TF32 tensor-core convs -> GN/relu -> mean -> linear
// B=256. ODE state [256,64,7,7]. Round-13 structure + conv-epilogue-fused
// group stats (register partials, no sB re-read).
// ---------------------------------------------------------------------------

#define EPSV 1e-5f

// ---- scratch layout (floats) ----
#define OFF_B1   0UL                      // 14745600
#define OFF_B2   14745600UL               // 3686400
#define OFF_Y    18432000UL               // 802816
#define OFF_K    19234816UL               // 6*802816 = 4816896
#define OFF_WF1  24051712UL               // 9216 float4 = 36864 floats
#define OFF_WF2  24088576UL               // 36864
#define OFF_TW1  24125440UL               // 3136
#define OFF_TW2  24128576UL               // 3136
#define OFF_WC2  24131712UL               // 16384 float4 = 65536 floats
#define OFF_WC3  24197248UL               // 65536
#define SCRATCH_TOTAL 24262784UL

__device__ float g_scratch[SCRATCH_TOTAL];

// ---------------------------------------------------------------------------
// tf32 helpers
// ---------------------------------------------------------------------------
__device__ __forceinline__ uint32_t f2tf32(float x) {
    uint32_t r; asm("cvt.rna.tf32.f32 %0, %1;" : "=r"(r) : "f"(x)); return r;
}
__device__ __forceinline__ float rnd_tf32(float x) {
    return __uint_as_float(f2tf32(x));
}
__device__ __forceinline__ void mma_tf32(float c[4],
    uint32_t a0, uint32_t a1, uint32_t a2, uint32_t a3,
    uint32_t b0, uint32_t b1)
{
    asm volatile("mma.sync.aligned.m16n8k8.row.col.f32.tf32.tf32.f32 "
        "{%0,%1,%2,%3}, {%4,%5,%6,%7}, {%8,%9}, {%0,%1,%2,%3};"
        : "+f"(c[0]), "+f"(c[1]), "+f"(c[2]), "+f"(c[3])
        : "r"(a0), "r"(a1), "r"(a2), "r"(a3), "r"(b0), "r"(b1));
}

// ---------------------------------------------------------------------------
// group stats helpers (32 groups, 8 threads/group; threads 0..255)
// ---------------------------------------------------------------------------
__device__ __forceinline__ void stats98(const float* __restrict__ s,
                                        float* __restrict__ sm,
                                        float* __restrict__ si, int tid)
{
    int g = tid >> 3, l = tid & 7;
    const float* p = s + g * 98;
    float su = 0.f, sq = 0.f;
    for (int j = l; j < 98; j += 8) { float v = p[j]; su += v; sq += v * v; }
    su += __shfl_xor_sync(0xffffffffu, su, 1); sq += __shfl_xor_sync(0xffffffffu, sq, 1);
    su += __shfl_xor_sync(0xffffffffu, su, 2); sq += __shfl_xor_sync(0xffffffffu, sq, 2);
    su += __shfl_xor_sync(0xffffffffu, su, 4); sq += __shfl_xor_sync(0xffffffffu, sq, 4);
    if (l == 0) {
        float m = su * (1.f / 98.f);
        float var = sq * (1.f / 98.f) - m * m;
        sm[g] = m; si[g] = rsqrtf(var + EPSV);
    }
}
__device__ __forceinline__ void stats450(const float* __restrict__ s,
                                         float* __restrict__ sm,
                                         float* __restrict__ si, int tid)
{
    int g = tid >> 3, l = tid & 7;
    const float* p = s + g * 450;
    float su = 0.f, sq = 0.f;
    for (int j = l; j < 450; j += 8) { float v = p[j]; su += v; sq += v * v; }
    su += __shfl_xor_sync(0xffffffffu, su, 1); sq += __shfl_xor_sync(0xffffffffu, sq, 1);
    su += __shfl_xor_sync(0xffffffffu, su, 2); sq += __shfl_xor_sync(0xffffffffu, sq, 2);
    su += __shfl_xor_sync(0xffffffffu, su, 4); sq += __shfl_xor_sync(0xffffffffu, sq, 4);
    if (l == 0) {
        float m = su * (1.f / 450.f);
        float var = sq * (1.f / 450.f) - m * m;
        sm[g] = m; si[g] = rsqrtf(var + EPSV);
    }
}

// ---------------------------------------------------------------------------
// prep: fragment-permute all tensor-core weights (single tf32, pair-packed)
// ---------------------------------------------------------------------------
__global__ void k_prep(const float* __restrict__ occ1_w, const float* __restrict__ occ2_w,
                       const float* __restrict__ c2_w, const float* __restrict__ c3_w,
                       float4* __restrict__ WF1, float4* __restrict__ WF2,
                       float* __restrict__ tw1, float* __restrict__ tw2,
                       float4* __restrict__ WC2, float4* __restrict__ WC3)
{
    int i = blockIdx.x * 256 + threadIdx.x;
    if (i < 9216) {
        int lane = i & 31, rem = i >> 5;
        int jp = rem & 3, tk = rem >> 2;
        int k = tk & 7, tap = tk >> 3;
        int ic0 = k * 8 + (lane & 3);
        int oc0 = 2 * jp * 8 + (lane >> 2);
        int oc1 = oc0 + 8;
        WF1[i] = make_float4(
            rnd_tf32(occ1_w[(oc0 * 65 + 1 + ic0) * 9 + tap]),
            rnd_tf32(occ1_w[(oc0 * 65 + 1 + ic0 + 4) * 9 + tap]),
            rnd_tf32(occ1_w[(oc1 * 65 + 1 + ic0) * 9 + tap]),
            rnd_tf32(occ1_w[(oc1 * 65 + 1 + ic0 + 4) * 9 + tap]));
        WF2[i] = make_float4(
            rnd_tf32(occ2_w[(oc0 * 65 + 1 + ic0) * 9 + tap]),
            rnd_tf32(occ2_w[(oc0 * 65 + 1 + ic0 + 4) * 9 + tap]),
            rnd_tf32(occ2_w[(oc1 * 65 + 1 + ic0) * 9 + tap]),
            rnd_tf32(occ2_w[(oc1 * 65 + 1 + ic0 + 4) * 9 + tap]));
    }
    if (i < 16384) {
        int lane = i & 31, rem = i >> 5;
        int p = rem & 3, tk = rem >> 2;
        int tap = tk & 15, chunk = tk >> 4;
        int ic = chunk * 8 + (lane & 3);
        int n0 = 2 * p * 8 + (lane >> 2);
        int n1 = n0 + 8;
        WC2[i] = make_float4(
            rnd_tf32(c2_w[(n0 * 64 + ic) * 16 + tap]),
            rnd_tf32(c2_w[(n0 * 64 + ic + 4) * 16 + tap]),
            rnd_tf32(c2_w[(n1 * 64 + ic) * 16 + tap]),
            rnd_tf32(c2_w[(n1 * 64 + ic + 4) * 16 + tap]));
        WC3[i] = make_float4(
            rnd_tf32(c3_w[(n0 * 64 + ic) * 16 + tap]),
            rnd_tf32(c3_w[(n0 * 64 + ic + 4) * 16 + tap]),
            rnd_tf32(c3_w[(n1 * 64 + ic) * 16 + tap]),
            rnd_tf32(c3_w[(n1 * 64 + ic + 4) * 16 + tap]));
    }
    if (i < 3136) {
        int oc = i / 49, pos = i % 49, oy = pos / 7, ox = pos % 7;
        float s1 = 0.f, s2 = 0.f;
        for (int ky = 0; ky < 3; ky++)
            for (int kx = 0; kx < 3; kx++) {
                int iy = oy + ky - 1, ix = ox + kx - 1;
                if ((unsigned)iy < 7u && (unsigned)ix < 7u) {
                    s1 += occ1_w[(oc * 65) * 9 + ky * 3 + kx];
                    s2 += occ2_w[(oc * 65) * 9 + ky * 3 + kx];
                }
            }
        tw1[i] = s1; tw2[i] = s2;
    }
}

// ---------------------------------------------------------------------------
// conv1 3->64 3x3 s1 p0 on 32x32 -> 30x30, fused GN + relu (fp32)
// ---------------------------------------------------------------------------
__global__ __launch_bounds__(128) void k_conv1(
    const float* __restrict__ x, const float* __restrict__ w,
    const float* __restrict__ bias, const float* __restrict__ gw,
    const float* __restrict__ gb, float* __restrict__ out)
{
    __shared__ float s_in[3 * 32 * 32];
    __shared__ float s_out[1800];
    __shared__ float s_w[54];
    __shared__ float sred[8];
    __shared__ float s_stats[2];
    int g = blockIdx.x, b = blockIdx.y, tid = threadIdx.x;
    for (int i = tid; i < 3072; i += 128) s_in[i] = x[b * 3072 + i];
    if (tid < 54) {
        int oc = 2 * g + tid / 27;
        s_w[tid] = w[oc * 27 + (tid % 27)];
    }
    __syncthreads();
    float mysum = 0.f, mysq = 0.f;
    for (int idx = tid; idx < 1800; idx += 128) {
        int c = idx / 900, pos = idx % 900, oy = pos / 30, ox = pos % 30;
        float acc = __ldg(&bias[2 * g + c]);
        const float* wp = &s_w[c * 27];
        #pragma unroll
        for (int ic = 0; ic < 3; ic++)
            #pragma unroll
            for (int ky = 0; ky < 3; ky++)
                #pragma unroll
                for (int kx = 0; kx < 3; kx++)
                    acc += wp[ic * 9 + ky * 3 + kx] * s_in[ic * 1024 + (oy + ky) * 32 + (ox + kx)];
        s_out[idx] = acc; mysum += acc; mysq += acc * acc;
    }
    #pragma unroll
    for (int o = 16; o > 0; o >>= 1) {
        mysum += __shfl_xor_sync(0xffffffffu, mysum, o);
        mysq  += __shfl_xor_sync(0xffffffffu, mysq,  o);
    }
    if ((tid & 31) == 0) { sred[(tid >> 5) * 2] = mysum; sred[(tid >> 5) * 2 + 1] = mysq; }
    __syncthreads();
    if (tid == 0) {
        float s = sred[0] + sred[2] + sred[4] + sred[6];
        float q = sred[1] + sred[3] + sred[5] + sred[7];
        float m = s / 1800.f, var = q / 1800.f - m * m;
        s_stats[0] = m; s_stats[1] = rsqrtf(var + EPSV);
    }
    __syncthreads();
    float m = s_stats[0], inv = s_stats[1];
    for (int idx = tid; idx < 1800; idx += 128) {
        int c = idx / 900, oc = 2 * g + c;
        float v = (s_out[idx] - m) * inv * __ldg(&gw[oc]) + __ldg(&gb[oc]);
        out[((size_t)b * 64 + oc) * 900 + (idx % 900)] = fmaxf(v, 0.f);
    }
}

// ---------------------------------------------------------------------------
// conv2 TF32: 64->64 4x4 s2 p1 on 30x30 -> 15x15, fused GN + relu.
// ---------------------------------------------------------------------------
#define C2_SMEM_FLOATS (10240 + 14400 + 64)
__global__ __launch_bounds__(256, 2) void k_conv2tc(
    const float* __restrict__ in, const float4* __restrict__ WC2,
    const float* __restrict__ bias, const float* __restrict__ gw,
    const float* __restrict__ gb, float* __restrict__ out)
{
    extern __shared__ float sc2[];
    float* sIn  = sc2;            // 1024 positions x stride 10 (tf32-rounded)
    float* sOut = sc2 + 10240;
    float* sm   = sc2 + 10240 + 14400;
    float* si   = sm + 32;
    const int b = blockIdx.x, tid = threadIdx.x;
    const int lane = tid & 31, wid = tid >> 5;
    const int icq = lane & 3;

    const int r00 = wid * 16 + (lane >> 2), r01 = r00 + 8;       // always < 225
    const int mt1 = wid + 8;
    const bool hasmt1 = mt1 < 15;
    const int r10 = mt1 * 16 + (lane >> 2), r11 = r10 + 8;
    const int p10 = min(r10, 224), p11 = min(r11, 224);
    const int oy00 = r00 / 15, ox00 = r00 % 15;
    const int oy01 = r01 / 15, ox01 = r01 % 15;
    const int oy10 = p10 / 15, ox10 = p10 % 15;
    const int oy11 = p11 / 15, ox11 = p11 % 15;

    float acc0[8][4], acc1[8][4];
    #pragma unroll
    for (int j = 0; j < 8; j++)
        #pragma unroll
        for (int q = 0; q < 4; q++) { acc0[j][q] = 0.f; acc1[j][q] = 0.f; }

    const float* inb = in + (size_t)b * 57600;
    for (int chunk = 0; chunk < 8; chunk++) {
        __syncthreads();
        for (int idx = tid; idx < 8192; idx += 256) {
            int icL = idx >> 10, pos = idx & 1023;
            int iy = pos >> 5, ix = pos & 31;
            int riy = iy - 1, rix = ix - 1;
            sIn[pos * 10 + icL] = ((unsigned)riy < 30u && (unsigned)rix < 30u)
                        ? rnd_tf32(inb[(chunk * 8 + icL) * 900 + riy * 30 + rix]) : 0.f;
        }
        __syncthreads();
        #pragma unroll 4
        for (int tap = 0; tap < 16; tap++) {
            int ky = tap >> 2, kx = tap & 3;
            int o00 = ((2 * oy00 + ky) * 32 + 2 * ox00 + kx) * 10 + icq;
            int o01 = ((2 * oy01 + ky) * 32 + 2 * ox01 + kx) * 10 + icq;
            int o10 = ((2 * oy10 + ky) * 32 + 2 * ox10 + kx) * 10 + icq;
            int o11 = ((2 * oy11 + ky) * 32 + 2 * ox11 + kx) * 10 + icq;
            uint32_t aA0 = __float_as_uint(sIn[o00]), aA1 = __float_as_uint(sIn[o01]);
            uint32_t aA2 = __float_as_uint(sIn[o00 + 4]), aA3 = __float_as_uint(sIn[o01 + 4]);
            uint32_t aB0 = __float_as_uint(sIn[o10]), aB1 = __float_as_uint(sIn[o11]);
            uint32_t aB2 = __float_as_uint(sIn[o10 + 4]), aB3 = __float_as_uint(sIn[o11 + 4]);
            const float4* wf = WC2 + ((size_t)(chunk * 16 + tap) * 4) * 32 + lane;
            #pragma unroll
            for (int p = 0; p < 4; p++) {
                float4 bv = __ldg(&wf[p * 32]);
                uint32_t b0 = __float_as_uint(bv.x), b1 = __float_as_uint(bv.y);
                uint32_t b2 = __float_as_uint(bv.z), b3 = __float_as_uint(bv.w);
                mma_tf32(acc0[2 * p],     aA0, aA1, aA2, aA3, b0, b1);
                mma_tf32(acc0[2 * p + 1], aA0, aA1, aA2, aA3, b2, b3);
                mma_tf32(acc1[2 * p],     aB0, aB1, aB2, aB3, b0, b1);
                mma_tf32(acc1[2 * p + 1], aB0, aB1, aB2, aB3, b2, b3);
            }
        }
    }
    __syncthreads();
    // scatter (bias included so GN stats see biased values)
    #pragma unroll
    for (int j = 0; j < 8; j++) {
        int n0 = j * 8 + 2 * (lane & 3);
        float b0 = __ldg(&bias[n0]), b1 = __ldg(&bias[n0 + 1]);
        sOut[n0 * 225 + r00] = acc0[j][0] + b0;
        sOut[(n0 + 1) * 225 + r00] = acc0[j][1] + b1;
        sOut[n0 * 225 + r01] = acc0[j][2] + b0;
        sOut[(n0 + 1) * 225 + r01] = acc0[j][3] + b1;
        if (hasmt1) {
            if (r10 < 225) {
                sOut[n0 * 225 + r10] = acc1[j][0] + b0;
                sOut[(n0 + 1) * 225 + r10] = acc1[j][1] + b1;
            }
            if (r11 < 225) {
                sOut[n0 * 225 + r11] = acc1[j][2] + b0;
                sOut[(n0 + 1) * 225 + r11] = acc1[j][3] + b1;
            }
        }
    }
    __syncthreads();
    stats450(sOut, sm, si, tid);
    __syncthreads();
    for (int i2 = tid; i2 < 14400; i2 += 256) {
        int oc = i2 / 225, g = oc >> 1;
        float v = (sOut[i2] - sm[g]) * si[g] * __ldg(&gw[oc]) + __ldg(&gb[oc]);
        out[(size_t)b * 14400 + i2] = fmaxf(v, 0.f);
    }
}

// ---------------------------------------------------------------------------
// conv3 TF32: 64->64 4x4 s2 p1 on 15x15 -> 7x7 (no GN).
// ---------------------------------------------------------------------------
#define C3_SMEM_FLOATS (256 * 66)
__global__ __launch_bounds__(256) void k_conv3tc(
    const float* __restrict__ in, const float4* __restrict__ WC3,
    const float* __restrict__ bias, float* __restrict__ out)
{
    extern __shared__ float sIn3[];   // 256 positions (16x16 padded) x stride 66
    const int b = blockIdx.x, tid = threadIdx.x;
    const int lane = tid & 31, wid = tid >> 5;
    const int mt = wid >> 1, nh = wid & 1;
    const int icq = lane & 3;
    const int r0 = mt * 16 + (lane >> 2), r1 = r0 + 8;
    const int p0 = min(r0, 48), p1 = min(r1, 48);
    const int oy0 = p0 / 7, ox0 = p0 % 7;
    const int oy1 = p1 / 7, ox1 = p1 % 7;

    float acc[4][4];
    #pragma unroll
    for (int j = 0; j < 4; j++)
        #pragma unroll
        for (int q = 0; q < 4; q++) acc[j][q] = 0.f;

    const float* inb = in + (size_t)b * 14400;
    for (int idx = tid; idx < 16384; idx += 256) {
        int ic = idx >> 8, pos = idx & 255;
        int iy = pos >> 4, ix = pos & 15;
        int riy = iy - 1, rix = ix - 1;
        sIn3[pos * 66 + ic] = ((unsigned)riy < 15u && (unsigned)rix < 15u)
                    ? rnd_tf32(inb[ic * 225 + riy * 15 + rix]) : 0.f;
    }
    __syncthreads();

    for (int chunk = 0; chunk < 8; chunk++) {
        #pragma unroll 4
        for (int tap = 0; tap < 16; tap++) {
            int ky = tap >> 2, kx = tap & 3;
            int o0 = ((2 * oy0 + ky) * 16 + 2 * ox0 + kx) * 66 + chunk * 8 + icq;
            int o1 = ((2 * oy1 + ky) * 16 + 2 * ox1 + kx) * 66 + chunk * 8 + icq;
            uint32_t a0 = __float_as_uint(sIn3[o0]), a1 = __float_as_uint(sIn3[o1]);
            uint32_t a2 = __float_as_uint(sIn3[o0 + 4]), a3 = __float_as_uint(sIn3[o1 + 4]);
            const float4* wf = WC3 + ((size_t)(chunk * 16 + tap) * 4 + nh * 2) * 32 + lane;
            #pragma unroll
            for (int p = 0; p < 2; p++) {
                float4 bv = __ldg(&wf[p * 32]);
                mma_tf32(acc[2 * p],     a0, a1, a2, a3,
                         __float_as_uint(bv.x), __float_as_uint(bv.y));
                mma_tf32(acc[2 * p + 1], a0, a1, a2, a3,
                         __float_as_uint(bv.z), __float_as_uint(bv.w));
            }
        }
    }
    #pragma unroll
    for (int j = 0; j < 4; j++) {
        int n = nh * 32 + j * 8 + 2 * (lane & 3);
        float b0 = __ldg(&bias[n]), b1 = __ldg(&bias[n + 1]);
        float* ob = out + (size_t)b * 3136;
        if (r0 < 49) {
            ob[n * 49 + r0] = acc[j][0] + b0;
            ob[(n + 1) * 49 + r0] = acc[j][1] + b1;
        }
        if (r1 < 49) {
            ob[n * 49 + r1] = acc[j][2] + b0;
            ob[(n + 1) * 49 + r1] = acc[j][3] + b1;
        }
    }
}

// ---------------------------------------------------------------------------
// fused ODE solver, 256 threads/image (8 warps), Round-13 warp map
// (ms=wid>>1 m-tile, nh=wid&1 n-half). Conv epilogues emit register-resident
// group-stat partials; 32-thread finalize replaces the stats98 read pass.
// ---------------------------------------------------------------------------
#define S_Y    0
#define S_ACT  3136
#define S_B    (3136 + 6936)
#define S_SM   (3136 + 6936 + 3136)
#define S_SI   (S_SM + 32)
#define S_PS   (S_SI + 32)
#define S_PQ   (S_PS + 128)
#define ODE_SMEM_FLOATS (S_PQ + 128)

__device__ __forceinline__ void conv_mma(
    const float* __restrict__ sAct, float* __restrict__ sB,
    float* __restrict__ sPS, float* __restrict__ sPQ,
    const float4* __restrict__ WF, const float* __restrict__ tW,
    const float* __restrict__ bias, float t,
    int pb_lo, int pb_hi, int row_lo, int row_hi,
    int c0i, int ms, int nh, int lane)
{
    float acc[4][4];
    #pragma unroll
    for (int j = 0; j < 4; j++) {
        int n0 = (nh * 4 + j) * 8 + 2 * (lane & 3);
        float b0v = __ldg(&bias[n0]), b1v = __ldg(&bias[n0 + 1]);
        acc[j][0] = (row_lo < 49) ? b0v + t * __ldg(&tW[n0 * 49 + row_lo]) : 0.f;
        acc[j][1] = (row_lo < 49) ? b1v + t * __ldg(&tW[(n0 + 1) * 49 + row_lo]) : 0.f;
        acc[j][2] = (row_hi < 49) ? b0v + t * __ldg(&tW[n0 * 49 + row_hi]) : 0.f;
        acc[j][3] = (row_hi < 49) ? b1v + t * __ldg(&tW[(n0 + 1) * 49 + row_hi]) : 0.f;
    }
    #pragma unroll 3
    for (int tap = 0; tap < 9; tap++) {
        int shift = (tap / 3) * 9 + (tap % 3) - 10;
        const float* aLo = sAct + (pb_lo + shift) * 68 + c0i;
        const float* aHi = sAct + (pb_hi + shift) * 68 + c0i;
        const float4* wf = WF + ((size_t)(tap * 8) * 4 + nh * 2) * 32 + lane;
        #pragma unroll
        for (int k = 0; k < 8; k++) {
            uint32_t a0 = __float_as_uint(aLo[k * 8]);
            uint32_t a1 = __float_as_uint(aHi[k * 8]);
            uint32_t a2 = __float_as_uint(aLo[k * 8 + 4]);
            uint32_t a3 = __float_as_uint(aHi[k * 8 + 4]);
            #pragma unroll
            for (int p = 0; p < 2; p++) {
                float4 bv = __ldg(&wf[(size_t)(k * 4 + p) * 32]);
                mma_tf32(acc[2 * p],     a0, a1, a2, a3,
                         __float_as_uint(bv.x), __float_as_uint(bv.y));
                mma_tf32(acc[2 * p + 1], a0, a1, a2, a3,
                         __float_as_uint(bv.z), __float_as_uint(bv.w));
            }
        }
    }
    #pragma unroll
    for (int j = 0; j < 4; j++) {
        int n0 = (nh * 4 + j) * 8 + 2 * (lane & 3);
        if (row_lo < 49) {
            sB[n0 * 49 + row_lo] = acc[j][0];
            sB[(n0 + 1) * 49 + row_lo] = acc[j][1];
        }
        if (row_hi < 49) {
            sB[n0 * 49 + row_hi] = acc[j][2];
            sB[(n0 + 1) * 49 + row_hi] = acc[j][3];
        }
    }
    // register-resident group-stat partials: group g_j = (nh*4+j)*4+(lane&3)
    #pragma unroll
    for (int j = 0; j < 4; j++) {
        float s = 0.f, q = 0.f;
        if (row_lo < 49) {
            s += acc[j][0] + acc[j][1];
            q += acc[j][0] * acc[j][0] + acc[j][1] * acc[j][1];
        }
        if (row_hi < 49) {
            s += acc[j][2] + acc[j][3];
            q += acc[j][2] * acc[j][2] + acc[j][3] * acc[j][3];
        }
        s += __shfl_xor_sync(0xffffffffu, s, 4);  q += __shfl_xor_sync(0xffffffffu, q, 4);
        s += __shfl_xor_sync(0xffffffffu, s, 8);  q += __shfl_xor_sync(0xffffffffu, q, 8);
        s += __shfl_xor_sync(0xffffffffu, s, 16); q += __shfl_xor_sync(0xffffffffu, q, 16);
        if ((lane >> 2) == 0) {
            int g = (nh * 4 + j) * 4 + (lane & 3);
            sPS[ms * 32 + g] = s;
            sPQ[ms * 32 + g] = q;
        }
    }
}

__global__ __launch_bounds__(256, 2) void k_ode(
    float* __restrict__ Yg, float* __restrict__ Kb,
    const float4* __restrict__ WF1, const float* __restrict__ TW1,
    const float* __restrict__ occ1_b,
    const float4* __restrict__ WF2, const float* __restrict__ TW2,
    const float* __restrict__ occ2_b,
    const float* __restrict__ oa_w, const float* __restrict__ oa_b,
    const float* __restrict__ ob_w, const float* __restrict__ ob_b,
    const float* __restrict__ oc_w, const float* __restrict__ oc_b)
{
    extern __shared__ float sd[];
    float* sY   = sd + S_Y;
    float* sAct = sd + S_ACT;
    float* sB   = sd + S_B;
    float* sm   = sd + S_SM;
    float* si   = sd + S_SI;
    float* sPS  = sd + S_PS;
    float* sPQ  = sd + S_PQ;

    const int b = blockIdx.x, tid = threadIdx.x;
    const int lane = tid & 31, wid = tid >> 5;
    const int ms = wid >> 1, nh = wid & 1;
    const int row_lo = ms * 16 + (lane >> 2);
    const int row_hi = row_lo + 8;
    const int pb_lo = (row_lo < 49) ? (row_lo / 7) * 9 + row_lo % 7 + 10 : 91;
    const int pb_hi = (row_hi < 49) ? (row_hi / 7) * 9 + row_hi % 7 + 10 : 91;
    const int c0i = lane & 3;
    const size_t base = (size_t)b * 3136;
    const int sg = tid >> 3, sl = tid & 7;   // stats group mapping

    const float ocw0 = __ldg(&oc_w[2 * sg]),     ocb0 = __ldg(&oc_b[2 * sg]);
    const float ocw1 = __ldg(&oc_w[2 * sg + 1]), ocb1 = __ldg(&oc_b[2 * sg + 1]);

    const double hh = 1.0 / 6.0;
    double Atab[6][5] = {
        {0, 0, 0, 0, 0},
        {1.0 / 5.0, 0, 0, 0, 0},
        {3.0 / 40.0, 9.0 / 40.0, 0, 0, 0},
        {44.0 / 45.0, -56.0 / 15.0, 32.0 / 9.0, 0, 0},
        {19372.0 / 6561.0, -25360.0 / 2187.0, 64448.0 / 6561.0, -212.0 / 729.0, 0},
        {9017.0 / 3168.0, -355.0 / 33.0, 46732.0 / 5247.0, 49.0 / 176.0, -5103.0 / 18656.0}
    };
    double Ctab[6] = {0.0, 1.0 / 5.0, 3.0 / 10.0, 4.0 / 5.0, 8.0 / 9.0, 1.0};

    for (int i = tid; i < 6936; i += 256) sAct[i] = 0.f;
    for (int i = tid; i < 3136; i += 256) sY[i] = Yg[base + i];
    __syncthreads();

    // initial combine (step 0, stage 0): sB = sY, fused stats
    {
        float su = 0.f, sq = 0.f;
        const int ibase = sg * 98;
        for (int j = sl; j < 98; j += 8) {
            float v = sY[ibase + j];
            sB[ibase + j] = v;
            su += v; sq += v * v;
        }
        su += __shfl_xor_sync(0xffffffffu, su, 1); sq += __shfl_xor_sync(0xffffffffu, sq, 1);
        su += __shfl_xor_sync(0xffffffffu, su, 2); sq += __shfl_xor_sync(0xffffffffu, sq, 2);
        su += __shfl_xor_sync(0xffffffffu, su, 4); sq += __shfl_xor_sync(0xffffffffu, sq, 4);
        if (sl == 0) {
            float m = su * (1.f / 98.f);
            float var = sq * (1.f / 98.f) - m * m;
            sm[sg] = m; si[sg] = rsqrtf(var + EPSV);
        }
    }
    __syncthreads();

    for (int step = 0; step < 6; step++) {
        double t0 = (double)step * hh;
        for (int s = 0; s < 6; s++) {
            float t = (float)(t0 + Ctab[s] * hh);

            // GN(oa)+relu -> sAct interior (tf32-pre-rounded)
            for (int i = tid; i < 3136; i += 256) {
                int pos = i >> 6, c = i & 63;
                int pb = (pos / 7) * 9 + pos % 7 + 10;
                int g = c >> 1;
                float v = (sB[c * 49 + pos] - sm[g]) * si[g] * __ldg(&oa_w[c]) + __ldg(&oa_b[c]);
                sAct[pb * 68 + c] = rnd_tf32(fmaxf(v, 0.f));
            }
            __syncthreads();
            conv_mma(sAct, sB, sPS, sPQ, WF1, TW1, occ1_b, t,
                     pb_lo, pb_hi, row_lo, row_hi, c0i, ms, nh, lane);
            __syncthreads();
            if (tid < 32) {
                float su = sPS[tid] + sPS[32 + tid] + sPS[64 + tid] + sPS[96 + tid];
                float sq = sPQ[tid] + sPQ[32 + tid] + sPQ[64 + tid] + sPQ[96 + tid];
                float m = su * (1.f / 98.f);
                float var = sq * (1.f / 98.f) - m * m;
                sm[tid] = m; si[tid] = rsqrtf(var + EPSV);
            }
            __syncthreads();
            for (int i = tid; i < 3136; i += 256) {
                int pos = i >> 6, c = i & 63;
                int pb = (pos / 7) * 9 + pos % 7 + 10;
                int g = c >> 1;
                float v = (sB[c * 49 + pos] - sm[g]) * si[g] * __ldg(&ob_w[c]) + __ldg(&ob_b[c]);
                sAct[pb * 68 + c] = rnd_tf32(fmaxf(v, 0.f));
            }
            __syncthreads();
            conv_mma(sAct, sB, sPS, sPQ, WF2, TW2, occ2_b, t,
                     pb_lo, pb_hi, row_lo, row_hi, c0i, ms, nh, lane);
            __syncthreads();
            if (tid < 32) {
                float su = sPS[tid] + sPS[32 + tid] + sPS[64 + tid] + sPS[96 + tid];
                float sq = sPQ[tid] + sPQ[32 + tid] + sPQ[64 + tid] + sPQ[96 + tid];
                float m = su * (1.f / 98.f);
                float var = sq * (1.f / 98.f) - m * m;
                sm[tid] = m; si[tid] = rsqrtf(var + EPSV);
            }
            __syncthreads();

            // fused epilogue: k = GN(oc)(sB); write K_s; combine next stage
            // (newest K from register); next-stage stats.
            {
                float m = sm[sg], inv = si[sg];
                float su = 0.f, sq = 0.f;
                const int ibase = sg * 98;
                if (s < 5) {
                    float cn0 = (float)(hh * Atab[s + 1][0]);
                    float cn1 = (float)(hh * Atab[s + 1][1]);
                    float cn2 = (float)(hh * Atab[s + 1][2]);
                    float cn3 = (float)(hh * Atab[s + 1][3]);
                    float cn4 = (float)(hh * Atab[s + 1][4]);
                    float cl = (s == 0) ? cn0 : (s == 1) ? cn1 : (s == 2) ? cn2
                             : (s == 3) ? cn3 : cn4;
                    float* Ks = Kb + (size_t)s * 802816 + base;
                    for (int j = sl; j < 98; j += 8) {
                        int i = ibase + j;
                        float ocw = (j < 49) ? ocw0 : ocw1;
                        float ocb = (j < 49) ? ocb0 : ocb1;
                        float kk = (sB[i] - m) * inv * ocw + ocb;
                        Ks[i] = kk;
                        float v = sY[i];
                        if (s >= 1) v += cn0 * Kb[base + i];
                        if (s >= 2) v += cn1 * Kb[802816 + base + i];
                        if (s >= 3) v += cn2 * Kb[2 * 802816 + base + i];
                        if (s >= 4) v += cn3 * Kb[3 * 802816 + base + i];
                        v += cl * kk;
                        sB[i] = v;
                        su += v; sq += v * v;
                    }
                } else {
                    float b1 = (float)(hh * 35.0 / 384.0);
                    float b3 = (float)(hh * 500.0 / 1113.0);
                    float b4 = (float)(hh * 125.0 / 192.0);
                    float b5 = (float)(hh * -2187.0 / 6784.0);
                    float b6 = (float)(hh * 11.0 / 84.0);
                    for (int j = sl; j < 98; j += 8) {
                        int i = ibase + j;
                        float ocw = (j < 49) ? ocw0 : ocw1;
                        float ocb = (j < 49) ? ocb0 : ocb1;
                        float k6 = (sB[i] - m) * inv * ocw + ocb;
                        float e = b1 * Kb[base + i]
                                + b3 * Kb[2 * 802816 + base + i]
                                + b4 * Kb[3 * 802816 + base + i]
                                + b5 * Kb[4 * 802816 + base + i]
                                + b6 * k6;
                        float v = sY[i] + e;
                        sY[i] = v;
                        sB[i] = v;
                        su += v; sq += v * v;
                    }
                }
                su += __shfl_xor_sync(0xffffffffu, su, 1); sq += __shfl_xor_sync(0xffffffffu, sq, 1);
                su += __shfl_xor_sync(0xffffffffu, su, 2); sq += __shfl_xor_sync(0xffffffffu, sq, 2);
                su += __shfl_xor_sync(0xffffffffu, su, 4); sq += __shfl_xor_sync(0xffffffffu, sq, 4);
                if (sl == 0) {
                    float mm = su * (1.f / 98.f);
                    float var = sq * (1.f / 98.f) - mm * mm;
                    sm[sg] = mm; si[sg] = rsqrtf(var + EPSV);
                }
            }
            __syncthreads();
        }
    }
    for (int i = tid; i < 3136; i += 256) Yg[base + i] = sY[i];
}

// ---------------------------------------------------------------------------
// tail: GN(g3)+relu -> spatial mean -> linear(64->10)
// ---------------------------------------------------------------------------
__global__ __launch_bounds__(256) void k_tail(
    const float* __restrict__ y, const float* __restrict__ gw,
    const float* __restrict__ gb, const float* __restrict__ lw,
    const float* __restrict__ lb, float* __restrict__ out)
{
    __shared__ float s[3136];
    __shared__ float sm[32], si[32];
    __shared__ float cm[64];
    int b = blockIdx.x, tid = threadIdx.x;
    const size_t base = (size_t)b * 3136;
    for (int i = tid; i < 3136; i += 256) s[i] = y[base + i];
    __syncthreads();
    stats98(s, sm, si, tid);
    __syncthreads();
    if (tid < 64) {
        int c = tid, g = c >> 1;
        float w = gw[c], bb = gb[c], m = sm[g], inv = si[g];
        float su = 0.f;
        #pragma unroll
        for (int j = 0; j < 49; j++)
            su += fmaxf((s[c * 49 + j] - m) * inv * w + bb, 0.f);
        cm[c] = su * (1.f / 49.f);
    }
    __syncthreads();
    if (tid < 10) {
        float o = lb[tid];
        #pragma unroll
        for (int c = 0; c < 64; c++) o += cm[c] * lw[tid * 64 + c];
        out[b * 10 + tid] = o;
    }
}

// ---------------------------------------------------------------------------
// host launcher
// ---------------------------------------------------------------------------
extern "C" void kernel_launch(void* const* d_in, const int* in_sizes, int n_in,
                              void* d_out, int out_size)
{
    const float* x      = (const float*)d_in[0];
    const float* c1_w   = (const float*)d_in[1];
    const float* c1_b   = (const float*)d_in[2];
    const float* g1_w   = (const float*)d_in[3];
    const float* g1_b   = (const float*)d_in[4];
    const float* c2_w   = (const float*)d_in[5];
    const float* c2_b   = (const float*)d_in[6];
    const float* g2_w   = (const float*)d_in[7];
    const float* g2_b   = (const float*)d_in[8];
    const float* c3_w   = (const float*)d_in[9];
    const float* c3_b   = (const float*)d_in[10];
    const float* oa_w   = (const float*)d_in[11];
    const float* oa_b   = (const float*)d_in[12];
    const float* occ1_w = (const float*)d_in[13];
    const float* occ1_b = (const float*)d_in[14];
    const float* ob_w   = (const float*)d_in[15];
    const float* ob_b   = (const float*)d_in[16];
    const float* occ2_w = (const float*)d_in[17];
    const float* occ2_b = (const float*)d_in[18];
    const float* oc_w   = (const float*)d_in[19];
    const float* oc_b   = (const float*)d_in[20];
    const float* g3_w   = (const float*)d_in[21];
    const float* g3_b   = (const float*)d_in[22];
    const float* lin_w  = (const float*)d_in[23];
    const float* lin_b  = (const float*)d_in[24];

    float* S = nullptr;
    cudaGetSymbolAddress((void**)&S, g_scratch);
    float*  B1  = S + OFF_B1;
    float*  B2  = S + OFF_B2;
    float*  Y   = S + OFF_Y;
    float*  Kb  = S + OFF_K;
    float4* WF1 = (float4*)(S + OFF_WF1);
    float4* WF2 = (float4*)(S + OFF_WF2);
    float*  TW1 = S + OFF_TW1;
    float*  TW2 = S + OFF_TW2;
    float4* WC2 = (float4*)(S + OFF_WC2);
    float4* WC3 = (float4*)(S + OFF_WC3);

    cudaFuncSetAttribute(k_ode, cudaFuncAttributeMaxDynamicSharedMemorySize,
                         ODE_SMEM_FLOATS * (int)sizeof(float));
    cudaFuncSetAttribute(k_conv2tc, cudaFuncAttributeMaxDynamicSharedMemorySize,
                         C2_SMEM_FLOATS * (int)sizeof(float));
    cudaFuncSetAttribute(k_conv3tc, cudaFuncAttributeMaxDynamicSharedMemorySize,
                         C3_SMEM_FLOATS * (int)sizeof(float));

    k_prep<<<64, 256>>>(occ1_w, occ2_w, c2_w, c3_w, WF1, WF2, TW1, TW2, WC2, WC3);
    k_conv1<<<dim3(32, 256), 128>>>(x, c1_w, c1_b, g1_w, g1_b, B1);
    k_conv2tc<<<256, 256, C2_SMEM_FLOATS * sizeof(float)>>>(B1, WC2, c2_b, g2_w, g2_b, B2);
    k_conv3tc<<<256, 256, C3_SMEM_FLOATS * sizeof(float)>>>(B2, WC3, c3_b, Y);
    k_ode<<<256, 256, ODE_SMEM_FLOATS * sizeof(float)>>>(
        Y, Kb, WF1, TW1, occ1_b, WF2, TW2, occ2_b,
        oa_w, oa_b, ob_w, ob_b, oc_w, oc_b);
    k_tail<<<256, 256>>>(Y, g3_w, g3_b, lin_w, lin_b, (float*)d_out);
}

// round 16
// speedup vs baseline: 1.1479x; 1.0312x over previous
#include <cuda_runtime.h>
#include <cstdint>

// ---------------------------------------------------------------------------
// ODEFullBlock: encoder (conv1 fp32; conv2/conv3 TF32 mma) -> fused dopri5 ODE
// solve with TF32 tensor-core convs -> GN/relu -> mean -> linear
// B=256. ODE state [256,64,7,7]. R15 structure + finalize-free stats
// (per-thread redundant group-stat reduction; 5 barriers/stage).
// ---------------------------------------------------------------------------

#define EPSV 1e-5f

// ---- scratch layout (floats) ----
#define OFF_B1   0UL                      // 14745600
#define OFF_B2   14745600UL               // 3686400
#define OFF_Y    18432000UL               // 802816
#define OFF_K    19234816UL               // 6*802816 = 4816896
#define OFF_WF1  24051712UL               // 9216 float4 = 36864 floats
#define OFF_WF2  24088576UL               // 36864
#define OFF_TW1  24125440UL               // 3136
#define OFF_TW2  24128576UL               // 3136
#define OFF_WC2  24131712UL               // 16384 float4 = 65536 floats
#define OFF_WC3  24197248UL               // 65536
#define SCRATCH_TOTAL 24262784UL

__device__ float g_scratch[SCRATCH_TOTAL];

// ---------------------------------------------------------------------------
// tf32 helpers
// ---------------------------------------------------------------------------
__device__ __forceinline__ uint32_t f2tf32(float x) {
    uint32_t r; asm("cvt.rna.tf32.f32 %0, %1;" : "=r"(r) : "f"(x)); return r;
}
__device__ __forceinline__ float rnd_tf32(float x) {
    return __uint_as_float(f2tf32(x));
}
__device__ __forceinline__ void mma_tf32(float c[4],
    uint32_t a0, uint32_t a1, uint32_t a2, uint32_t a3,
    uint32_t b0, uint32_t b1)
{
    asm volatile("mma.sync.aligned.m16n8k8.row.col.f32.tf32.tf32.f32 "
        "{%0,%1,%2,%3}, {%4,%5,%6,%7}, {%8,%9}, {%0,%1,%2,%3};"
        : "+f"(c[0]), "+f"(c[1]), "+f"(c[2]), "+f"(c[3])
        : "r"(a0), "r"(a1), "r"(a2), "r"(a3), "r"(b0), "r"(b1));
}

// ---------------------------------------------------------------------------
// group stats helpers (32 groups, 8 threads/group; threads 0..255)
// ---------------------------------------------------------------------------
__device__ __forceinline__ void stats98(const float* __restrict__ s,
                                        float* __restrict__ sm,
                                        float* __restrict__ si, int tid)
{
    int g = tid >> 3, l = tid & 7;
    const float* p = s + g * 98;
    float su = 0.f, sq = 0.f;
    for (int j = l; j < 98; j += 8) { float v = p[j]; su += v; sq += v * v; }
    su += __shfl_xor_sync(0xffffffffu, su, 1); sq += __shfl_xor_sync(0xffffffffu, sq, 1);
    su += __shfl_xor_sync(0xffffffffu, su, 2); sq += __shfl_xor_sync(0xffffffffu, sq, 2);
    su += __shfl_xor_sync(0xffffffffu, su, 4); sq += __shfl_xor_sync(0xffffffffu, sq, 4);
    if (l == 0) {
        float m = su * (1.f / 98.f);
        float var = sq * (1.f / 98.f) - m * m;
        sm[g] = m; si[g] = rsqrtf(var + EPSV);
    }
}
__device__ __forceinline__ void stats450(const float* __restrict__ s,
                                         float* __restrict__ sm,
                                         float* __restrict__ si, int tid)
{
    int g = tid >> 3, l = tid & 7;
    const float* p = s + g * 450;
    float su = 0.f, sq = 0.f;
    for (int j = l; j < 450; j += 8) { float v = p[j]; su += v; sq += v * v; }
    su += __shfl_xor_sync(0xffffffffu, su, 1); sq += __shfl_xor_sync(0xffffffffu, sq, 1);
    su += __shfl_xor_sync(0xffffffffu, su, 2); sq += __shfl_xor_sync(0xffffffffu, sq, 2);
    su += __shfl_xor_sync(0xffffffffu, su, 4); sq += __shfl_xor_sync(0xffffffffu, sq, 4);
    if (l == 0) {
        float m = su * (1.f / 450.f);
        float var = sq * (1.f / 450.f) - m * m;
        sm[g] = m; si[g] = rsqrtf(var + EPSV);
    }
}

// ---------------------------------------------------------------------------
// prep: fragment-permute all tensor-core weights (single tf32, pair-packed)
// ---------------------------------------------------------------------------
__global__ void k_prep(const float* __restrict__ occ1_w, const float* __restrict__ occ2_w,
                       const float* __restrict__ c2_w, const float* __restrict__ c3_w,
                       float4* __restrict__ WF1, float4* __restrict__ WF2,
                       float* __restrict__ tw1, float* __restrict__ tw2,
                       float4* __restrict__ WC2, float4* __restrict__ WC3)
{
    int i = blockIdx.x * 256 + threadIdx.x;
    if (i < 9216) {
        int lane = i & 31, rem = i >> 5;
        int jp = rem & 3, tk = rem >> 2;
        int k = tk & 7, tap = tk >> 3;
        int ic0 = k * 8 + (lane & 3);
        int oc0 = 2 * jp * 8 + (lane >> 2);
        int oc1 = oc0 + 8;
        WF1[i] = make_float4(
            rnd_tf32(occ1_w[(oc0 * 65 + 1 + ic0) * 9 + tap]),
            rnd_tf32(occ1_w[(oc0 * 65 + 1 + ic0 + 4) * 9 + tap]),
            rnd_tf32(occ1_w[(oc1 * 65 + 1 + ic0) * 9 + tap]),
            rnd_tf32(occ1_w[(oc1 * 65 + 1 + ic0 + 4) * 9 + tap]));
        WF2[i] = make_float4(
            rnd_tf32(occ2_w[(oc0 * 65 + 1 + ic0) * 9 + tap]),
            rnd_tf32(occ2_w[(oc0 * 65 + 1 + ic0 + 4) * 9 + tap]),
            rnd_tf32(occ2_w[(oc1 * 65 + 1 + ic0) * 9 + tap]),
            rnd_tf32(occ2_w[(oc1 * 65 + 1 + ic0 + 4) * 9 + tap]));
    }
    if (i < 16384) {
        int lane = i & 31, rem = i >> 5;
        int p = rem & 3, tk = rem >> 2;
        int tap = tk & 15, chunk = tk >> 4;
        int ic = chunk * 8 + (lane & 3);
        int n0 = 2 * p * 8 + (lane >> 2);
        int n1 = n0 + 8;
        WC2[i] = make_float4(
            rnd_tf32(c2_w[(n0 * 64 + ic) * 16 + tap]),
            rnd_tf32(c2_w[(n0 * 64 + ic + 4) * 16 + tap]),
            rnd_tf32(c2_w[(n1 * 64 + ic) * 16 + tap]),
            rnd_tf32(c2_w[(n1 * 64 + ic + 4) * 16 + tap]));
        WC3[i] = make_float4(
            rnd_tf32(c3_w[(n0 * 64 + ic) * 16 + tap]),
            rnd_tf32(c3_w[(n0 * 64 + ic + 4) * 16 + tap]),
            rnd_tf32(c3_w[(n1 * 64 + ic) * 16 + tap]),
            rnd_tf32(c3_w[(n1 * 64 + ic + 4) * 16 + tap]));
    }
    if (i < 3136) {
        int oc = i / 49, pos = i % 49, oy = pos / 7, ox = pos % 7;
        float s1 = 0.f, s2 = 0.f;
        for (int ky = 0; ky < 3; ky++)
            for (int kx = 0; kx < 3; kx++) {
                int iy = oy + ky - 1, ix = ox + kx - 1;
                if ((unsigned)iy < 7u && (unsigned)ix < 7u) {
                    s1 += occ1_w[(oc * 65) * 9 + ky * 3 + kx];
                    s2 += occ2_w[(oc * 65) * 9 + ky * 3 + kx];
                }
            }
        tw1[i] = s1; tw2[i] = s2;
    }
}

// ---------------------------------------------------------------------------
// conv1 3->64 3x3 s1 p0 on 32x32 -> 30x30, fused GN + relu (fp32)
// ---------------------------------------------------------------------------
__global__ __launch_bounds__(128) void k_conv1(
    const float* __restrict__ x, const float* __restrict__ w,
    const float* __restrict__ bias, const float* __restrict__ gw,
    const float* __restrict__ gb, float* __restrict__ out)
{
    __shared__ float s_in[3 * 32 * 32];
    __shared__ float s_out[1800];
    __shared__ float s_w[54];
    __shared__ float sred[8];
    __shared__ float s_stats[2];
    int g = blockIdx.x, b = blockIdx.y, tid = threadIdx.x;
    for (int i = tid; i < 3072; i += 128) s_in[i] = x[b * 3072 + i];
    if (tid < 54) {
        int oc = 2 * g + tid / 27;
        s_w[tid] = w[oc * 27 + (tid % 27)];
    }
    __syncthreads();
    float mysum = 0.f, mysq = 0.f;
    for (int idx = tid; idx < 1800; idx += 128) {
        int c = idx / 900, pos = idx % 900, oy = pos / 30, ox = pos % 30;
        float acc = __ldg(&bias[2 * g + c]);
        const float* wp = &s_w[c * 27];
        #pragma unroll
        for (int ic = 0; ic < 3; ic++)
            #pragma unroll
            for (int ky = 0; ky < 3; ky++)
                #pragma unroll
                for (int kx = 0; kx < 3; kx++)
                    acc += wp[ic * 9 + ky * 3 + kx] * s_in[ic * 1024 + (oy + ky) * 32 + (ox + kx)];
        s_out[idx] = acc; mysum += acc; mysq += acc * acc;
    }
    #pragma unroll
    for (int o = 16; o > 0; o >>= 1) {
        mysum += __shfl_xor_sync(0xffffffffu, mysum, o);
        mysq  += __shfl_xor_sync(0xffffffffu, mysq,  o);
    }
    if ((tid & 31) == 0) { sred[(tid >> 5) * 2] = mysum; sred[(tid >> 5) * 2 + 1] = mysq; }
    __syncthreads();
    if (tid == 0) {
        float s = sred[0] + sred[2] + sred[4] + sred[6];
        float q = sred[1] + sred[3] + sred[5] + sred[7];
        float m = s / 1800.f, var = q / 1800.f - m * m;
        s_stats[0] = m; s_stats[1] = rsqrtf(var + EPSV);
    }
    __syncthreads();
    float m = s_stats[0], inv = s_stats[1];
    for (int idx = tid; idx < 1800; idx += 128) {
        int c = idx / 900, oc = 2 * g + c;
        float v = (s_out[idx] - m) * inv * __ldg(&gw[oc]) + __ldg(&gb[oc]);
        out[((size_t)b * 64 + oc) * 900 + (idx % 900)] = fmaxf(v, 0.f);
    }
}

// ---------------------------------------------------------------------------
// conv2 TF32: 64->64 4x4 s2 p1 on 30x30 -> 15x15, fused GN + relu.
// ---------------------------------------------------------------------------
#define C2_SMEM_FLOATS (10240 + 14400 + 64)
__global__ __launch_bounds__(256, 2) void k_conv2tc(
    const float* __restrict__ in, const float4* __restrict__ WC2,
    const float* __restrict__ bias, const float* __restrict__ gw,
    const float* __restrict__ gb, float* __restrict__ out)
{
    extern __shared__ float sc2[];
    float* sIn  = sc2;            // 1024 positions x stride 10 (tf32-rounded)
    float* sOut = sc2 + 10240;
    float* sm   = sc2 + 10240 + 14400;
    float* si   = sm + 32;
    const int b = blockIdx.x, tid = threadIdx.x;
    const int lane = tid & 31, wid = tid >> 5;
    const int icq = lane & 3;

    const int r00 = wid * 16 + (lane >> 2), r01 = r00 + 8;       // always < 225
    const int mt1 = wid + 8;
    const bool hasmt1 = mt1 < 15;
    const int r10 = mt1 * 16 + (lane >> 2), r11 = r10 + 8;
    const int p10 = min(r10, 224), p11 = min(r11, 224);
    const int oy00 = r00 / 15, ox00 = r00 % 15;
    const int oy01 = r01 / 15, ox01 = r01 % 15;
    const int oy10 = p10 / 15, ox10 = p10 % 15;
    const int oy11 = p11 / 15, ox11 = p11 % 15;

    float acc0[8][4], acc1[8][4];
    #pragma unroll
    for (int j = 0; j < 8; j++)
        #pragma unroll
        for (int q = 0; q < 4; q++) { acc0[j][q] = 0.f; acc1[j][q] = 0.f; }

    const float* inb = in + (size_t)b * 57600;
    for (int chunk = 0; chunk < 8; chunk++) {
        __syncthreads();
        for (int idx = tid; idx < 8192; idx += 256) {
            int icL = idx >> 10, pos = idx & 1023;
            int iy = pos >> 5, ix = pos & 31;
            int riy = iy - 1, rix = ix - 1;
            sIn[pos * 10 + icL] = ((unsigned)riy < 30u && (unsigned)rix < 30u)
                        ? rnd_tf32(inb[(chunk * 8 + icL) * 900 + riy * 30 + rix]) : 0.f;
        }
        __syncthreads();
        #pragma unroll 4
        for (int tap = 0; tap < 16; tap++) {
            int ky = tap >> 2, kx = tap & 3;
            int o00 = ((2 * oy00 + ky) * 32 + 2 * ox00 + kx) * 10 + icq;
            int o01 = ((2 * oy01 + ky) * 32 + 2 * ox01 + kx) * 10 + icq;
            int o10 = ((2 * oy10 + ky) * 32 + 2 * ox10 + kx) * 10 + icq;
            int o11 = ((2 * oy11 + ky) * 32 + 2 * ox11 + kx) * 10 + icq;
            uint32_t aA0 = __float_as_uint(sIn[o00]), aA1 = __float_as_uint(sIn[o01]);
            uint32_t aA2 = __float_as_uint(sIn[o00 + 4]), aA3 = __float_as_uint(sIn[o01 + 4]);
            uint32_t aB0 = __float_as_uint(sIn[o10]), aB1 = __float_as_uint(sIn[o11]);
            uint32_t aB2 = __float_as_uint(sIn[o10 + 4]), aB3 = __float_as_uint(sIn[o11 + 4]);
            const float4* wf = WC2 + ((size_t)(chunk * 16 + tap) * 4) * 32 + lane;
            #pragma unroll
            for (int p = 0; p < 4; p++) {
                float4 bv = __ldg(&wf[p * 32]);
                uint32_t b0 = __float_as_uint(bv.x), b1 = __float_as_uint(bv.y);
                uint32_t b2 = __float_as_uint(bv.z), b3 = __float_as_uint(bv.w);
                mma_tf32(acc0[2 * p],     aA0, aA1, aA2, aA3, b0, b1);
                mma_tf32(acc0[2 * p + 1], aA0, aA1, aA2, aA3, b2, b3);
                mma_tf32(acc1[2 * p],     aB0, aB1, aB2, aB3, b0, b1);
                mma_tf32(acc1[2 * p + 1], aB0, aB1, aB2, aB3, b2, b3);
            }
        }
    }
    __syncthreads();
    // scatter (bias included so GN stats see biased values)
    #pragma unroll
    for (int j = 0; j < 8; j++) {
        int n0 = j * 8 + 2 * (lane & 3);
        float b0 = __ldg(&bias[n0]), b1 = __ldg(&bias[n0 + 1]);
        sOut[n0 * 225 + r00] = acc0[j][0] + b0;
        sOut[(n0 + 1) * 225 + r00] = acc0[j][1] + b1;
        sOut[n0 * 225 + r01] = acc0[j][2] + b0;
        sOut[(n0 + 1) * 225 + r01] = acc0[j][3] + b1;
        if (hasmt1) {
            if (r10 < 225) {
                sOut[n0 * 225 + r10] = acc1[j][0] + b0;
                sOut[(n0 + 1) * 225 + r10] = acc1[j][1] + b1;
            }
            if (r11 < 225) {
                sOut[n0 * 225 + r11] = acc1[j][2] + b0;
                sOut[(n0 + 1) * 225 + r11] = acc1[j][3] + b1;
            }
        }
    }
    __syncthreads();
    stats450(sOut, sm, si, tid);
    __syncthreads();
    for (int i2 = tid; i2 < 14400; i2 += 256) {
        int oc = i2 / 225, g = oc >> 1;
        float v = (sOut[i2] - sm[g]) * si[g] * __ldg(&gw[oc]) + __ldg(&gb[oc]);
        out[(size_t)b * 14400 + i2] = fmaxf(v, 0.f);
    }
}

// ---------------------------------------------------------------------------
// conv3 TF32: 64->64 4x4 s2 p1 on 15x15 -> 7x7 (no GN).
// ---------------------------------------------------------------------------
#define C3_SMEM_FLOATS (256 * 66)
__global__ __launch_bounds__(256) void k_conv3tc(
    const float* __restrict__ in, const float4* __restrict__ WC3,
    const float* __restrict__ bias, float* __restrict__ out)
{
    extern __shared__ float sIn3[];   // 256 positions (16x16 padded) x stride 66
    const int b = blockIdx.x, tid = threadIdx.x;
    const int lane = tid & 31, wid = tid >> 5;
    const int mt = wid >> 1, nh = wid & 1;
    const int icq = lane & 3;
    const int r0 = mt * 16 + (lane >> 2), r1 = r0 + 8;
    const int p0 = min(r0, 48), p1 = min(r1, 48);
    const int oy0 = p0 / 7, ox0 = p0 % 7;
    const int oy1 = p1 / 7, ox1 = p1 % 7;

    float acc[4][4];
    #pragma unroll
    for (int j = 0; j < 4; j++)
        #pragma unroll
        for (int q = 0; q < 4; q++) acc[j][q] = 0.f;

    const float* inb = in + (size_t)b * 14400;
    for (int idx = tid; idx < 16384; idx += 256) {
        int ic = idx >> 8, pos = idx & 255;
        int iy = pos >> 4, ix = pos & 15;
        int riy = iy - 1, rix = ix - 1;
        sIn3[pos * 66 + ic] = ((unsigned)riy < 15u && (unsigned)rix < 15u)
                    ? rnd_tf32(inb[ic * 225 + riy * 15 + rix]) : 0.f;
    }
    __syncthreads();

    for (int chunk = 0; chunk < 8; chunk++) {
        #pragma unroll 4
        for (int tap = 0; tap < 16; tap++) {
            int ky = tap >> 2, kx = tap & 3;
            int o0 = ((2 * oy0 + ky) * 16 + 2 * ox0 + kx) * 66 + chunk * 8 + icq;
            int o1 = ((2 * oy1 + ky) * 16 + 2 * ox1 + kx) * 66 + chunk * 8 + icq;
            uint32_t a0 = __float_as_uint(sIn3[o0]), a1 = __float_as_uint(sIn3[o1]);
            uint32_t a2 = __float_as_uint(sIn3[o0 + 4]), a3 = __float_as_uint(sIn3[o1 + 4]);
            const float4* wf = WC3 + ((size_t)(chunk * 16 + tap) * 4 + nh * 2) * 32 + lane;
            #pragma unroll
            for (int p = 0; p < 2; p++) {
                float4 bv = __ldg(&wf[p * 32]);
                mma_tf32(acc[2 * p],     a0, a1, a2, a3,
                         __float_as_uint(bv.x), __float_as_uint(bv.y));
                mma_tf32(acc[2 * p + 1], a0, a1, a2, a3,
                         __float_as_uint(bv.z), __float_as_uint(bv.w));
            }
        }
    }
    #pragma unroll
    for (int j = 0; j < 4; j++) {
        int n = nh * 32 + j * 8 + 2 * (lane & 3);
        float b0 = __ldg(&bias[n]), b1 = __ldg(&bias[n + 1]);
        float* ob = out + (size_t)b * 3136;
        if (r0 < 49) {
            ob[n * 49 + r0] = acc[j][0] + b0;
            ob[(n + 1) * 49 + r0] = acc[j][1] + b1;
        }
        if (r1 < 49) {
            ob[n * 49 + r1] = acc[j][2] + b0;
            ob[(n + 1) * 49 + r1] = acc[j][3] + b1;
        }
    }
}

// ---------------------------------------------------------------------------
// fused ODE solver, 256 threads/image (8 warps), finalize-free stats.
// 5 barriers/stage.
// ---------------------------------------------------------------------------
#define S_Y    0
#define S_ACT  3136
#define S_B    (3136 + 6936)
#define S_SM   (3136 + 6936 + 3136)
#define S_SI   (S_SM + 32)
#define S_PS   (S_SI + 32)
#define S_PQ   (S_PS + 128)
#define S_PB   (S_PQ + 128)
#define ODE_SMEM_FLOATS (S_PB + 64)

__device__ __forceinline__ void conv_mma(
    const float* __restrict__ sAct, float* __restrict__ sB,
    float* __restrict__ sPS, float* __restrict__ sPQ,
    const float4* __restrict__ WF, const float* __restrict__ tW,
    const float* __restrict__ bias, float t,
    int pb_lo, int pb_hi, int row_lo, int row_hi,
    int c0i, int ms, int nh, int lane)
{
    float acc[4][4];
    #pragma unroll
    for (int j = 0; j < 4; j++) {
        int n0 = (nh * 4 + j) * 8 + 2 * (lane & 3);
        float b0v = __ldg(&bias[n0]), b1v = __ldg(&bias[n0 + 1]);
        acc[j][0] = (row_lo < 49) ? b0v + t * __ldg(&tW[n0 * 49 + row_lo]) : 0.f;
        acc[j][1] = (row_lo < 49) ? b1v + t * __ldg(&tW[(n0 + 1) * 49 + row_lo]) : 0.f;
        acc[j][2] = (row_hi < 49) ? b0v + t * __ldg(&tW[n0 * 49 + row_hi]) : 0.f;
        acc[j][3] = (row_hi < 49) ? b1v + t * __ldg(&tW[(n0 + 1) * 49 + row_hi]) : 0.f;
    }
    #pragma unroll 3
    for (int tap = 0; tap < 9; tap++) {
        int shift = (tap / 3) * 9 + (tap % 3) - 10;
        const float* aLo = sAct + (pb_lo + shift) * 68 + c0i;
        const float* aHi = sAct + (pb_hi + shift) * 68 + c0i;
        const float4* wf = WF + ((size_t)(tap * 8) * 4 + nh * 2) * 32 + lane;
        #pragma unroll
        for (int k = 0; k < 8; k++) {
            uint32_t a0 = __float_as_uint(aLo[k * 8]);
            uint32_t a1 = __float_as_uint(aHi[k * 8]);
            uint32_t a2 = __float_as_uint(aLo[k * 8 + 4]);
            uint32_t a3 = __float_as_uint(aHi[k * 8 + 4]);
            #pragma unroll
            for (int p = 0; p < 2; p++) {
                float4 bv = __ldg(&wf[(size_t)(k * 4 + p) * 32]);
                mma_tf32(acc[2 * p],     a0, a1, a2, a3,
                         __float_as_uint(bv.x), __float_as_uint(bv.y));
                mma_tf32(acc[2 * p + 1], a0, a1, a2, a3,
                         __float_as_uint(bv.z), __float_as_uint(bv.w));
            }
        }
    }
    #pragma unroll
    for (int j = 0; j < 4; j++) {
        int n0 = (nh * 4 + j) * 8 + 2 * (lane & 3);
        if (row_lo < 49) {
            sB[n0 * 49 + row_lo] = acc[j][0];
            sB[(n0 + 1) * 49 + row_lo] = acc[j][1];
        }
        if (row_hi < 49) {
            sB[n0 * 49 + row_hi] = acc[j][2];
            sB[(n0 + 1) * 49 + row_hi] = acc[j][3];
        }
    }
    // register-resident group-stat partials: group g_j = (nh*4+j)*4+(lane&3)
    #pragma unroll
    for (int j = 0; j < 4; j++) {
        float s = 0.f, q = 0.f;
        if (row_lo < 49) {
            s += acc[j][0] + acc[j][1];
            q += acc[j][0] * acc[j][0] + acc[j][1] * acc[j][1];
        }
        if (row_hi < 49) {
            s += acc[j][2] + acc[j][3];
            q += acc[j][2] * acc[j][2] + acc[j][3] * acc[j][3];
        }
        s += __shfl_xor_sync(0xffffffffu, s, 4);  q += __shfl_xor_sync(0xffffffffu, q, 4);
        s += __shfl_xor_sync(0xffffffffu, s, 8);  q += __shfl_xor_sync(0xffffffffu, q, 8);
        s += __shfl_xor_sync(0xffffffffu, s, 16); q += __shfl_xor_sync(0xffffffffu, q, 16);
        if ((lane >> 2) == 0) {
            int g = (nh * 4 + j) * 4 + (lane & 3);
            sPS[ms * 32 + g] = s;
            sPQ[ms * 32 + g] = q;
        }
    }
}

__global__ __launch_bounds__(256, 2) void k_ode(
    float* __restrict__ Yg, float* __restrict__ Kb,
    const float4* __restrict__ WF1, const float* __restrict__ TW1,
    const float* __restrict__ occ1_b,
    const float4* __restrict__ WF2, const float* __restrict__ TW2,
    const float* __restrict__ occ2_b,
    const float* __restrict__ oa_w, const float* __restrict__ oa_b,
    const float* __restrict__ ob_w, const float* __restrict__ ob_b,
    const float* __restrict__ oc_w, const float* __restrict__ oc_b)
{
    extern __shared__ float sd[];
    float* sY   = sd + S_Y;
    float* sAct = sd + S_ACT;
    float* sB   = sd + S_B;
    float* sm   = sd + S_SM;
    float* si   = sd + S_SI;
    float* sPS  = sd + S_PS;
    float* sPQ  = sd + S_PQ;
    int*   sPB  = (int*)(sd + S_PB);

    const int b = blockIdx.x, tid = threadIdx.x;
    const int lane = tid & 31, wid = tid >> 5;
    const int ms = wid >> 1, nh = wid & 1;
    const int row_lo = ms * 16 + (lane >> 2);
    const int row_hi = row_lo + 8;
    const int pb_lo = (row_lo < 49) ? (row_lo / 7) * 9 + row_lo % 7 + 10 : 91;
    const int pb_hi = (row_hi < 49) ? (row_hi / 7) * 9 + row_hi % 7 + 10 : 91;
    const int c0i = lane & 3;
    const size_t base = (size_t)b * 3136;
    const int sg = tid >> 3, sl = tid & 7;   // stats group mapping
    const int cc = tid & 63, cg = cc >> 1;   // fixed channel for elementwise passes
    const int posq = tid >> 6;               // starting pos (0..3)

    const float ocw0 = __ldg(&oc_w[2 * sg]),     ocb0 = __ldg(&oc_b[2 * sg]);
    const float ocw1 = __ldg(&oc_w[2 * sg + 1]), ocb1 = __ldg(&oc_b[2 * sg + 1]);
    const float oawc = __ldg(&oa_w[cc]), oabc = __ldg(&oa_b[cc]);
    const float obwc = __ldg(&ob_w[cc]), obbc = __ldg(&ob_b[cc]);

    const double hh = 1.0 / 6.0;
    double Atab[6][5] = {
        {0, 0, 0, 0, 0},
        {1.0 / 5.0, 0, 0, 0, 0},
        {3.0 / 40.0, 9.0 / 40.0, 0, 0, 0},
        {44.0 / 45.0, -56.0 / 15.0, 32.0 / 9.0, 0, 0},
        {19372.0 / 6561.0, -25360.0 / 2187.0, 64448.0 / 6561.0, -212.0 / 729.0, 0},
        {9017.0 / 3168.0, -355.0 / 33.0, 46732.0 / 5247.0, 49.0 / 176.0, -5103.0 / 18656.0}
    };
    double Ctab[6] = {0.0, 1.0 / 5.0, 3.0 / 10.0, 4.0 / 5.0, 8.0 / 9.0, 1.0};

    for (int i = tid; i < 6936; i += 256) sAct[i] = 0.f;
    for (int i = tid; i < 3136; i += 256) sY[i] = Yg[base + i];
    if (tid < 49) sPB[tid] = (tid / 7) * 9 + tid % 7 + 10;
    __syncthreads();

    // initial combine (step 0, stage 0): sB = sY, fused stats
    {
        float su = 0.f, sq = 0.f;
        const int ibase = sg * 98;
        for (int j = sl; j < 98; j += 8) {
            float v = sY[ibase + j];
            sB[ibase + j] = v;
            su += v; sq += v * v;
        }
        su += __shfl_xor_sync(0xffffffffu, su, 1); sq += __shfl_xor_sync(0xffffffffu, sq, 1);
        su += __shfl_xor_sync(0xffffffffu, su, 2); sq += __shfl_xor_sync(0xffffffffu, sq, 2);
        su += __shfl_xor_sync(0xffffffffu, su, 4); sq += __shfl_xor_sync(0xffffffffu, sq, 4);
        if (sl == 0) {
            float m = su * (1.f / 98.f);
            float var = sq * (1.f / 98.f) - m * m;
            sm[sg] = m; si[sg] = rsqrtf(var + EPSV);
        }
    }
    __syncthreads();

    for (int step = 0; step < 6; step++) {
        double t0 = (double)step * hh;
        for (int s = 0; s < 6; s++) {
            float t = (float)(t0 + Ctab[s] * hh);

            // GN(oa)+relu -> sAct (stats from sm/si written by epilogue)
            {
                float m = sm[cg], inv = si[cg];
                const float* sBc = sB + cc * 49;
                for (int pos = posq; pos < 49; pos += 4) {
                    float v = (sBc[pos] - m) * inv * oawc + oabc;
                    sAct[sPB[pos] * 68 + cc] = rnd_tf32(fmaxf(v, 0.f));
                }
            }
            __syncthreads();
            conv_mma(sAct, sB, sPS, sPQ, WF1, TW1, occ1_b, t,
                     pb_lo, pb_hi, row_lo, row_hi, c0i, ms, nh, lane);
            __syncthreads();
            // GN(ob)+relu -> sAct (stats computed per-thread from sPS/sPQ)
            {
                float su4 = sPS[cg] + sPS[32 + cg] + sPS[64 + cg] + sPS[96 + cg];
                float sq4 = sPQ[cg] + sPQ[32 + cg] + sPQ[64 + cg] + sPQ[96 + cg];
                float m = su4 * (1.f / 98.f);
                float var = sq4 * (1.f / 98.f) - m * m;
                float inv = rsqrtf(var + EPSV);
                const float* sBc = sB + cc * 49;
                for (int pos = posq; pos < 49; pos += 4) {
                    float v = (sBc[pos] - m) * inv * obwc + obbc;
                    sAct[sPB[pos] * 68 + cc] = rnd_tf32(fmaxf(v, 0.f));
                }
            }
            __syncthreads();
            conv_mma(sAct, sB, sPS, sPQ, WF2, TW2, occ2_b, t,
                     pb_lo, pb_hi, row_lo, row_hi, c0i, ms, nh, lane);
            __syncthreads();

            // fused epilogue: stats from sPS/sPQ; k = GN(oc)(sB); write K_s;
            // combine next stage (newest K from register); next-stage stats.
            {
                float su4 = sPS[sg] + sPS[32 + sg] + sPS[64 + sg] + sPS[96 + sg];
                float sq4 = sPQ[sg] + sPQ[32 + sg] + sPQ[64 + sg] + sPQ[96 + sg];
                float m = su4 * (1.f / 98.f);
                float var = sq4 * (1.f / 98.f) - m * m;
                float inv = rsqrtf(var + EPSV);
                float su = 0.f, sq = 0.f;
                const int ibase = sg * 98;
                if (s < 5) {
                    float cn0 = (float)(hh * Atab[s + 1][0]);
                    float cn1 = (float)(hh * Atab[s + 1][1]);
                    float cn2 = (float)(hh * Atab[s + 1][2]);
                    float cn3 = (float)(hh * Atab[s + 1][3]);
                    float cn4 = (float)(hh * Atab[s + 1][4]);
                    float cl = (s == 0) ? cn0 : (s == 1) ? cn1 : (s == 2) ? cn2
                             : (s == 3) ? cn3 : cn4;
                    float* Ks = Kb + (size_t)s * 802816 + base;
                    for (int j = sl; j < 98; j += 8) {
                        int i = ibase + j;
                        float ocw = (j < 49) ? ocw0 : ocw1;
                        float ocb = (j < 49) ? ocb0 : ocb1;
                        float kk = (sB[i] - m) * inv * ocw + ocb;
                        Ks[i] = kk;
                        float v = sY[i];
                        if (s >= 1) v += cn0 * Kb[base + i];
                        if (s >= 2) v += cn1 * Kb[802816 + base + i];
                        if (s >= 3) v += cn2 * Kb[2 * 802816 + base + i];
                        if (s >= 4) v += cn3 * Kb[3 * 802816 + base + i];
                        v += cl * kk;
                        sB[i] = v;
                        su += v; sq += v * v;
                    }
                } else {
                    float b1 = (float)(hh * 35.0 / 384.0);
                    float b3 = (float)(hh * 500.0 / 1113.0);
                    float b4 = (float)(hh * 125.0 / 192.0);
                    float b5 = (float)(hh * -2187.0 / 6784.0);
                    float b6 = (float)(hh * 11.0 / 84.0);
                    for (int j = sl; j < 98; j += 8) {
                        int i = ibase + j;
                        float ocw = (j < 49) ? ocw0 : ocw1;
                        float ocb = (j < 49) ? ocb0 : ocb1;
                        float k6 = (sB[i] - m) * inv * ocw + ocb;
                        float e = b1 * Kb[base + i]
                                + b3 * Kb[2 * 802816 + base + i]
                                + b4 * Kb[3 * 802816 + base + i]
                                + b5 * Kb[4 * 802816 + base + i]
                                + b6 * k6;
                        float v = sY[i] + e;
                        sY[i] = v;
                        sB[i] = v;
                        su += v; sq += v * v;
                    }
                }
                su += __shfl_xor_sync(0xffffffffu, su, 1); sq += __shfl_xor_sync(0xffffffffu, sq, 1);
                su += __shfl_xor_sync(0xffffffffu, su, 2); sq += __shfl_xor_sync(0xffffffffu, sq, 2);
                su += __shfl_xor_sync(0xffffffffu, su, 4); sq += __shfl_xor_sync(0xffffffffu, sq, 4);
                if (sl == 0) {
                    float mm = su * (1.f / 98.f);
                    float var2 = sq * (1.f / 98.f) - mm * mm;
                    sm[sg] = mm; si[sg] = rsqrtf(var2 + EPSV);
                }
            }
            __syncthreads();
        }
    }
    for (int i = tid; i < 3136; i += 256) Yg[base + i] = sY[i];
}

// ---------------------------------------------------------------------------
// tail: GN(g3)+relu -> spatial mean -> linear(64->10)
// ---------------------------------------------------------------------------
__global__ __launch_bounds__(256) void k_tail(
    const float* __restrict__ y, const float* __restrict__ gw,
    const float* __restrict__ gb, const float* __restrict__ lw,
    const float* __restrict__ lb, float* __restrict__ out)
{
    __shared__ float s[3136];
    __shared__ float sm[32], si[32];
    __shared__ float cm[64];
    int b = blockIdx.x, tid = threadIdx.x;
    const size_t base = (size_t)b * 3136;
    for (int i = tid; i < 3136; i += 256) s[i] = y[base + i];
    __syncthreads();
    stats98(s, sm, si, tid);
    __syncthreads();
    if (tid < 64) {
        int c = tid, g = c >> 1;
        float w = gw[c], bb = gb[c], m = sm[g], inv = si[g];
        float su = 0.f;
        #pragma unroll
        for (int j = 0; j < 49; j++)
            su += fmaxf((s[c * 49 + j] - m) * inv * w + bb, 0.f);
        cm[c] = su * (1.f / 49.f);
    }
    __syncthreads();
    if (tid < 10) {
        float o = lb[tid];
        #pragma unroll
        for (int c = 0; c < 64; c++) o += cm[c] * lw[tid * 64 + c];
        out[b * 10 + tid] = o;
    }
}

// ---------------------------------------------------------------------------
// host launcher
// ---------------------------------------------------------------------------
extern "C" void kernel_launch(void* const* d_in, const int* in_sizes, int n_in,
                              void* d_out, int out_size)
{
    const float* x      = (const float*)d_in[0];
    const float* c1_w   = (const float*)d_in[1];
    const float* c1_b   = (const float*)d_in[2];
    const float* g1_w   = (const float*)d_in[3];
    const float* g1_b   = (const float*)d_in[4];
    const float* c2_w   = (const float*)d_in[5];
    const float* c2_b   = (const float*)d_in[6];
    const float* g2_w   = (const float*)d_in[7];
    const float* g2_b   = (const float*)d_in[8];
    const float* c3_w   = (const float*)d_in[9];
    const float* c3_b   = (const float*)d_in[10];
    const float* oa_w   = (const float*)d_in[11];
    const float* oa_b   = (const float*)d_in[12];
    const float* occ1_w = (const float*)d_in[13];
    const float* occ1_b = (const float*)d_in[14];
    const float* ob_w   = (const float*)d_in[15];
    const float* ob_b   = (const float*)d_in[16];
    const float* occ2_w = (const float*)d_in[17];
    const float* occ2_b = (const float*)d_in[18];
    const float* oc_w   = (const float*)d_in[19];
    const float* oc_b   = (const float*)d_in[20];
    const float* g3_w   = (const float*)d_in[21];
    const float* g3_b   = (const float*)d_in[22];
    const float* lin_w  = (const float*)d_in[23];
    const float* lin_b  = (const float*)d_in[24];

    float* S = nullptr;
    cudaGetSymbolAddress((void**)&S, g_scratch);
    float*  B1  = S + OFF_B1;
    float*  B2  = S + OFF_B2;
    float*  Y   = S + OFF_Y;
    float*  Kb  = S + OFF_K;
    float4* WF1 = (float4*)(S + OFF_WF1);
    float4* WF2 = (float4*)(S + OFF_WF2);
    float*  TW1 = S + OFF_TW1;
    float*  TW2 = S + OFF_TW2;
    float4* WC2 = (float4*)(S + OFF_WC2);
    float4* WC3 = (float4*)(S + OFF_WC3);

    cudaFuncSetAttribute(k_ode, cudaFuncAttributeMaxDynamicSharedMemorySize,
                         ODE_SMEM_FLOATS * (int)sizeof(float));
    cudaFuncSetAttribute(k_conv2tc, cudaFuncAttributeMaxDynamicSharedMemorySize,
                         C2_SMEM_FLOATS * (int)sizeof(float));
    cudaFuncSetAttribute(k_conv3tc, cudaFuncAttributeMaxDynamicSharedMemorySize,
                         C3_SMEM_FLOATS * (int)sizeof(float));

    k_prep<<<64, 256>>>(occ1_w, occ2_w, c2_w, c3_w, WF1, WF2, TW1, TW2, WC2, WC3);
    k_conv1<<<dim3(32, 256), 128>>>(x, c1_w, c1_b, g1_w, g1_b, B1);
    k_conv2tc<<<256, 256, C2_SMEM_FLOATS * sizeof(float)>>>(B1, WC2, c2_b, g2_w, g2_b, B2);
    k_conv3tc<<<256, 256, C3_SMEM_FLOATS * sizeof(float)>>>(B2, WC3, c3_b, Y);
    k_ode<<<256, 256, ODE_SMEM_FLOATS * sizeof(float)>>>(
        Y, Kb, WF1, TW1, occ1_b, WF2, TW2, occ2_b,
        oa_w, oa_b, ob_w, ob_b, oc_w, oc_b);
    k_tail<<<256, 256>>>(Y, g3_w, g3_b, lin_w, lin_b, (float*)d_out);
}